// round 13
// baseline (speedup 1.0000x reference)
#include <cuda_runtime.h>
#include <cuda_fp16.h>
#include <math.h>
#include <cstdint>

#define N_USERS 100000
#define N_ITEMS 50000
#define N_NODES 150000
#define EMB 64
#define NINT 128
#define MAX_EDGES 4000000

#define N4 ((N_NODES + 3) / 4)
#define NBLK ((N4 + 1023) / 1024)

// ---------------- static device scratch ----------------
__device__ int    g_deg[N_NODES];
__device__ float  g_dis[N_NODES];
__device__ int    g_rowptr[N_NODES + 1];
__device__ int    g_cursor[N_NODES];
__device__ int    g_ecol[MAX_EDGES];
__device__ volatile unsigned long long g_state[NBLK];
__device__ float  g_embA[(size_t)N_NODES * EMB];
__device__ float  g_embB[(size_t)N_NODES * EMB];
__device__ __half g_embS0[(size_t)N_NODES * EMB];  // layer0 spmm input
__device__ __half g_embS1[(size_t)N_NODES * EMB];  // layer1 spmm input

// ---------------- packed fp32x2 helpers ----------------
__device__ __forceinline__ unsigned long long fma2(unsigned long long a,
                                                   unsigned long long b,
                                                   unsigned long long c) {
    unsigned long long d;
    asm("fma.rn.f32x2 %0, %1, %2, %3;" : "=l"(d) : "l"(a), "l"(b), "l"(c));
    return d;
}
__device__ __forceinline__ unsigned long long pk2(float x, float y) {
    unsigned long long r;
    asm("mov.b64 %0, {%1, %2};" : "=l"(r) : "f"(x), "f"(y));
    return r;
}
__device__ __forceinline__ float2 upk(unsigned long long v) {
    float2 f;
    asm("mov.b64 {%0, %1}, %2;" : "=f"(f.x), "=f"(f.y) : "l"(v));
    return f;
}
__device__ __forceinline__ unsigned long long h2f2(unsigned int h) {
    float2 f = __half22float2(*(const __half2*)&h);
    return pk2(f.x, f.y);
}

// ---------------- precompute ----------------
__global__ void hist_kernel(const int* __restrict__ h, int n) {
    int stride = gridDim.x * blockDim.x;
    for (int i = blockIdx.x * blockDim.x + threadIdx.x; i < n; i += stride)
        atomicAdd(&g_deg[h[i]], 1);
}

__global__ __launch_bounds__(1024) void scan_kernel(int n_edges) {
    __shared__ int ws[32];
    __shared__ int s_excl;
    const int t = threadIdx.x, b = blockIdx.x;
    const int lane = t & 31, wid = t >> 5;
    const int idx = b * 1024 + t;
    int4 v = (idx < N4) ? ((const int4*)g_deg)[idx] : make_int4(0, 0, 0, 0);
    int s = v.x + v.y + v.z + v.w;
    int x = s;
    #pragma unroll
    for (int o = 1; o < 32; o <<= 1) {
        int y = __shfl_up_sync(0xffffffffu, x, o);
        if (lane >= o) x += y;
    }
    if (lane == 31) ws[wid] = x;
    __syncthreads();
    if (wid == 0) {
        int z = ws[lane];
        #pragma unroll
        for (int o = 1; o < 32; o <<= 1) {
            int y = __shfl_up_sync(0xffffffffu, z, o);
            if (lane >= o) z += y;
        }
        ws[lane] = z;
    }
    __syncthreads();
    const int total = ws[31];

    if (t == 0) {
        if (b == 0) {
            g_state[0] = (2ull << 32) | (unsigned)total;
            s_excl = 0;
        } else {
            g_state[b] = (1ull << 32) | (unsigned)total;
            int excl = 0;
            int p = b - 1;
            while (true) {
                unsigned long long st;
                do { st = g_state[p]; } while ((st >> 32) == 0ull);
                excl += (int)(unsigned)st;
                if ((st >> 32) == 2ull) break;
                p--;
            }
            g_state[b] = (2ull << 32) | (unsigned)(excl + total);
            s_excl = excl;
        }
    }
    __syncthreads();

    int base = s_excl + ((wid > 0) ? ws[wid - 1] : 0) + (x - s);
    if (idx < N4) {
        int i = idx * 4;
        int e0 = base, e1 = e0 + v.x, e2 = e1 + v.y, e3 = e2 + v.z;
        g_rowptr[i + 0] = e0; g_cursor[i + 0] = e0;
        g_rowptr[i + 1] = e1; g_cursor[i + 1] = e1;
        g_rowptr[i + 2] = e2; g_cursor[i + 2] = e2;
        g_rowptr[i + 3] = e3; g_cursor[i + 3] = e3;
        g_dis[i + 0] = (v.x > 0) ? rsqrtf((float)v.x) : 0.0f;
        g_dis[i + 1] = (v.y > 0) ? rsqrtf((float)v.y) : 0.0f;
        g_dis[i + 2] = (v.z > 0) ? rsqrtf((float)v.z) : 0.0f;
        g_dis[i + 3] = (v.w > 0) ? rsqrtf((float)v.w) : 0.0f;
    }
    if (b == 0 && t == 0) g_rowptr[N_NODES] = n_edges;
}

__global__ void scatter_init_kernel(const int* __restrict__ h, const int* __restrict__ t,
                                    int n,
                                    const float* __restrict__ u, const float* __restrict__ it,
                                    float* __restrict__ embA, float* __restrict__ out,
                                    __half* __restrict__ S) {
    const int stride = gridDim.x * blockDim.x;
    const int tid0 = blockIdx.x * blockDim.x + threadIdx.x;
    const int total4 = N_NODES * EMB / 4;
    const int ub4 = N_USERS * EMB / 4;
    const float third = 1.0f / 3.0f;
    for (int i = tid0; i < total4; i += stride) {
        float4 v = (i < ub4) ? ((const float4*)u)[i] : ((const float4*)it)[i - ub4];
        ((float4*)embA)[i] = v;
        ((float4*)out)[i] = make_float4(v.x * third, v.y * third, v.z * third, v.w * third);
        float d = g_dis[i >> 4];
        ((__half2*)S)[i * 2 + 0] = __floats2half2_rn(v.x * d, v.y * d);
        ((__half2*)S)[i * 2 + 1] = __floats2half2_rn(v.z * d, v.w * d);
    }
    for (int i = tid0; i < n; i += stride) {
        int hh = h[i];
        int pos = atomicAdd(&g_cursor[hh], 1);
        g_ecol[pos] = t[i];
    }
}

// ================ fused layer kernel: spmm + intent + epilogue ================
// Per 128-node tile:
//   warp w gathers spmm for its own 16 nodes -> smem gnn (fp32)
//   phase1 L = X @ W (mma.sync), softmax in regs, phase2 Y = P @ W^T
//   epilogue: y = gnn + Y; emb_out = y; out += y/3; Sout = half(dis*y)
// Sin and Sout are DISTINCT buffers (double-buffered across layers).

#define OFF_WT 0               // W^T [128j][72d] fp16 = 18432 B
#define OFF_W2 18432           // W   [64d][136j] fp16 = 17408 B
#define OFF_X  35840           // X   [128m][72d] fp16 = 18432 B
#define OFF_G  54272           // gnn [128m][68]  fp32 = 34816 B
#define SMEM_FL 89088
#define WTLDB 144
#define W2LDB 272
#define XLDB  144
#define GLD   68

__device__ __forceinline__ uint32_t pack_h2(float x, float y) {
    __half2 h = __floats2half2_rn(x, y);
    return *(uint32_t*)&h;
}
__device__ __forceinline__ void ldmx4(uint32_t addr, uint32_t& r0, uint32_t& r1,
                                      uint32_t& r2, uint32_t& r3) {
    asm volatile("ldmatrix.sync.aligned.m8n8.x4.shared.b16 {%0,%1,%2,%3}, [%4];"
                 : "=r"(r0), "=r"(r1), "=r"(r2), "=r"(r3) : "r"(addr));
}
__device__ __forceinline__ void ldmx2(uint32_t addr, uint32_t& r0, uint32_t& r1) {
    asm volatile("ldmatrix.sync.aligned.m8n8.x2.shared.b16 {%0,%1}, [%2];"
                 : "=r"(r0), "=r"(r1) : "r"(addr));
}
__device__ __forceinline__ void mma16816(float& c0, float& c1, float& c2, float& c3,
                                         uint32_t a0, uint32_t a1, uint32_t a2, uint32_t a3,
                                         uint32_t b0, uint32_t b1) {
    asm volatile("mma.sync.aligned.m16n8k16.row.col.f32.f16.f16.f32 "
                 "{%0,%1,%2,%3}, {%4,%5,%6,%7}, {%8,%9}, {%0,%1,%2,%3};"
                 : "+f"(c0), "+f"(c1), "+f"(c2), "+f"(c3)
                 : "r"(a0), "r"(a1), "r"(a2), "r"(a3), "r"(b0), "r"(b1));
}

__global__ __launch_bounds__(256, 2) void fused_layer_kernel(
    const float* __restrict__ xin, const __half* __restrict__ Sin,
    const float* __restrict__ W,
    float* __restrict__ emb_out, float* __restrict__ out,
    __half* __restrict__ Sout) {
    extern __shared__ char smem[];
    __half* hWT = (__half*)(smem + OFF_WT);
    __half* hW2 = (__half*)(smem + OFF_W2);
    __half* hX  = (__half*)(smem + OFF_X);
    float*  sG  = (float*)(smem + OFF_G);
    const uint32_t sb = (uint32_t)__cvta_generic_to_shared(smem);

    const int tid = threadIdx.x;
    const int w = tid >> 5, lane = tid & 31;
    const int node0 = blockIdx.x * 128;

    // ---- stage W^T, W, X (fp16) ----
    for (int i = tid; i < 64 * 128; i += 256) {
        int d = i >> 7, j = i & 127;
        hWT[j * 72 + d] = __float2half(W[i]);
    }
    for (int i2 = tid; i2 < 64 * 64; i2 += 256) {
        int d = i2 >> 6, j2 = i2 & 63;
        float2 v = *(const float2*)(W + d * 128 + j2 * 2);
        ((__half2*)hW2)[d * 68 + j2] = __floats2half2_rn(v.x, v.y);
    }
    for (int i2 = tid; i2 < 128 * 32; i2 += 256) {
        int m = i2 >> 5, d2 = i2 & 31;
        int nd = node0 + m;
        float2 v = (nd < N_NODES) ? *(const float2*)(xin + (size_t)nd * EMB + d2 * 2)
                                  : make_float2(0.f, 0.f);
        ((__half2*)hX)[m * 36 + d2] = __floats2half2_rn(v.x, v.y);
    }

    // ---- spmm: warp w gathers its own 16 nodes into sG ----
    {
        const int grp = lane >> 3;          // edge slot within quad
        const int q = lane & 7;             // 16B slice of the fp16 row
        const uint4* S4 = (const uint4*)Sin;
        const unsigned long long one2 = 0x3f8000003f800000ull;
        #pragma unroll 1
        for (int i = 0; i < 16; i++) {
            const int m = w * 16 + i;
            const int n = node0 + m;
            if (n >= N_NODES) break;
            const int beg = g_rowptr[n], end = g_rowptr[n + 1];
            unsigned long long a0 = 0ull, a1 = 0ull, a2 = 0ull, a3 = 0ull;
            int j = beg;
            const int nq = (end - beg) >> 2;
            if (nq > 0) {
                int c = g_ecol[j + grp];
                uint4 v = S4[(size_t)c * 8 + q];
                for (int b = 1; b < nq; b++) {
                    j += 4;
                    int d = g_ecol[j + grp];
                    uint4 nx = S4[(size_t)d * 8 + q];
                    a0 = fma2(h2f2(v.x), one2, a0);
                    a1 = fma2(h2f2(v.y), one2, a1);
                    a2 = fma2(h2f2(v.z), one2, a2);
                    a3 = fma2(h2f2(v.w), one2, a3);
                    v = nx;
                }
                a0 = fma2(h2f2(v.x), one2, a0);
                a1 = fma2(h2f2(v.y), one2, a1);
                a2 = fma2(h2f2(v.z), one2, a2);
                a3 = fma2(h2f2(v.w), one2, a3);
                j += 4;
            }
            if (j + grp < end) {
                int c = g_ecol[j + grp];
                uint4 v = S4[(size_t)c * 8 + q];
                a0 = fma2(h2f2(v.x), one2, a0);
                a1 = fma2(h2f2(v.y), one2, a1);
                a2 = fma2(h2f2(v.z), one2, a2);
                a3 = fma2(h2f2(v.w), one2, a3);
            }
            float2 f0 = upk(a0), f1 = upk(a1), f2 = upk(a2), f3 = upk(a3);
            #pragma unroll
            for (int o = 8; o <= 16; o <<= 1) {
                f0.x += __shfl_xor_sync(0xffffffffu, f0.x, o);
                f0.y += __shfl_xor_sync(0xffffffffu, f0.y, o);
                f1.x += __shfl_xor_sync(0xffffffffu, f1.x, o);
                f1.y += __shfl_xor_sync(0xffffffffu, f1.y, o);
                f2.x += __shfl_xor_sync(0xffffffffu, f2.x, o);
                f2.y += __shfl_xor_sync(0xffffffffu, f2.y, o);
                f3.x += __shfl_xor_sync(0xffffffffu, f3.x, o);
                f3.y += __shfl_xor_sync(0xffffffffu, f3.y, o);
            }
            if (grp == 0) {
                float dn = g_dis[n];
                float* row = sG + m * GLD + q * 8;
                *(float4*)(row)     = make_float4(f0.x * dn, f0.y * dn, f1.x * dn, f1.y * dn);
                *(float4*)(row + 4) = make_float4(f2.x * dn, f2.y * dn, f3.x * dn, f3.y * dn);
            }
        }
    }
    __syncthreads();

    // ---- phase 1: warp w owns rows m0..m0+16; logits acc[16 n-tiles][4] ----
    const int m0 = w * 16;
    float acc[16][4];
    #pragma unroll
    for (int n = 0; n < 16; n++) {
        acc[n][0] = 0.f; acc[n][1] = 0.f; acc[n][2] = 0.f; acc[n][3] = 0.f;
    }
    const uint32_t xrow = (uint32_t)(m0 + (lane & 7) + 8 * ((lane >> 3) & 1));
    const uint32_t xaddr0 = sb + OFF_X + xrow * XLDB + (uint32_t)(lane >> 4) * 16;
    const uint32_t brow_in = (uint32_t)(lane & 7);
    const uint32_t bmat = (uint32_t)((lane >> 3) & 1) * 16;

    #pragma unroll
    for (int kf = 0; kf < 4; kf++) {
        uint32_t a0, a1, a2, a3;
        ldmx4(xaddr0 + kf * 32, a0, a1, a2, a3);
        #pragma unroll
        for (int n = 0; n < 16; n++) {
            uint32_t b0, b1;
            uint32_t baddr = sb + OFF_WT + (n * 8 + brow_in) * WTLDB + kf * 32 + bmat;
            ldmx2(baddr, b0, b1);
            mma16816(acc[n][0], acc[n][1], acc[n][2], acc[n][3], a0, a1, a2, a3, b0, b1);
        }
    }

    // ---- softmax in registers ----
    float mx_lo = -1e30f, mx_hi = -1e30f;
    #pragma unroll
    for (int n = 0; n < 16; n++) {
        mx_lo = fmaxf(mx_lo, fmaxf(acc[n][0], acc[n][1]));
        mx_hi = fmaxf(mx_hi, fmaxf(acc[n][2], acc[n][3]));
    }
    mx_lo = fmaxf(mx_lo, __shfl_xor_sync(0xffffffffu, mx_lo, 1));
    mx_lo = fmaxf(mx_lo, __shfl_xor_sync(0xffffffffu, mx_lo, 2));
    mx_hi = fmaxf(mx_hi, __shfl_xor_sync(0xffffffffu, mx_hi, 1));
    mx_hi = fmaxf(mx_hi, __shfl_xor_sync(0xffffffffu, mx_hi, 2));
    float s_lo = 0.f, s_hi = 0.f;
    #pragma unroll
    for (int n = 0; n < 16; n++) {
        acc[n][0] = __expf(acc[n][0] - mx_lo); s_lo += acc[n][0];
        acc[n][1] = __expf(acc[n][1] - mx_lo); s_lo += acc[n][1];
        acc[n][2] = __expf(acc[n][2] - mx_hi); s_hi += acc[n][2];
        acc[n][3] = __expf(acc[n][3] - mx_hi); s_hi += acc[n][3];
    }
    s_lo += __shfl_xor_sync(0xffffffffu, s_lo, 1);
    s_lo += __shfl_xor_sync(0xffffffffu, s_lo, 2);
    s_hi += __shfl_xor_sync(0xffffffffu, s_hi, 1);
    s_hi += __shfl_xor_sync(0xffffffffu, s_hi, 2);
    const float inv_lo = 1.0f / s_lo, inv_hi = 1.0f / s_hi;

    // ---- repack scaled accs directly as phase2 A fragments ----
    uint32_t A2[8][4];
    #pragma unroll
    for (int kf2 = 0; kf2 < 8; kf2++) {
        A2[kf2][0] = pack_h2(acc[2 * kf2][0] * inv_lo,     acc[2 * kf2][1] * inv_lo);
        A2[kf2][1] = pack_h2(acc[2 * kf2][2] * inv_hi,     acc[2 * kf2][3] * inv_hi);
        A2[kf2][2] = pack_h2(acc[2 * kf2 + 1][0] * inv_lo, acc[2 * kf2 + 1][1] * inv_lo);
        A2[kf2][3] = pack_h2(acc[2 * kf2 + 1][2] * inv_hi, acc[2 * kf2 + 1][3] * inv_hi);
    }

    // ---- phase 2: Y = P @ W^T ----
    float acc2[8][4];
    #pragma unroll
    for (int n2 = 0; n2 < 8; n2++) {
        acc2[n2][0] = 0.f; acc2[n2][1] = 0.f; acc2[n2][2] = 0.f; acc2[n2][3] = 0.f;
    }
    #pragma unroll
    for (int kf2 = 0; kf2 < 8; kf2++) {
        #pragma unroll
        for (int n2 = 0; n2 < 8; n2++) {
            uint32_t b0, b1;
            uint32_t baddr = sb + OFF_W2 + (n2 * 8 + brow_in) * W2LDB + kf2 * 32 + bmat;
            ldmx2(baddr, b0, b1);
            mma16816(acc2[n2][0], acc2[n2][1], acc2[n2][2], acc2[n2][3],
                     A2[kf2][0], A2[kf2][1], A2[kf2][2], A2[kf2][3], b0, b1);
        }
    }

    // ---- epilogue: y = gnn(smem) + Y; emb_out = y; out += y/3; Sout = half(dis*y) ----
    const float third = 1.0f / 3.0f;
    const int ml = m0 + (lane >> 2);       // local row (lo)
    const int r_lo = node0 + ml;
    const int r_hi = r_lo + 8;
    const int q2 = (lane & 3) * 2;
    const float d_lo = (Sout && r_lo < N_NODES) ? g_dis[r_lo] : 0.0f;
    const float d_hi = (Sout && r_hi < N_NODES) ? g_dis[r_hi] : 0.0f;
    #pragma unroll
    for (int n2 = 0; n2 < 8; n2++) {
        int dcol = n2 * 8 + q2;
        if (r_lo < N_NODES) {
            float2 g = *(const float2*)(sG + ml * GLD + dcol);
            float y0 = acc2[n2][0] + g.x, y1 = acc2[n2][1] + g.y;
            size_t idx = (size_t)r_lo * EMB + dcol;
            if (emb_out) *(float2*)(emb_out + idx) = make_float2(y0, y1);
            float2 o = *(const float2*)(out + idx);
            *(float2*)(out + idx) = make_float2(o.x + y0 * third, o.y + y1 * third);
            if (Sout) *(__half2*)(Sout + idx) = __floats2half2_rn(y0 * d_lo, y1 * d_lo);
        }
        if (r_hi < N_NODES) {
            float2 g = *(const float2*)(sG + (ml + 8) * GLD + dcol);
            float y0 = acc2[n2][2] + g.x, y1 = acc2[n2][3] + g.y;
            size_t idx = (size_t)r_hi * EMB + dcol;
            if (emb_out) *(float2*)(emb_out + idx) = make_float2(y0, y1);
            float2 o = *(const float2*)(out + idx);
            *(float2*)(out + idx) = make_float2(o.x + y0 * third, o.y + y1 * third);
            if (Sout) *(__half2*)(Sout + idx) = __floats2half2_rn(y0 * d_hi, y1 * d_hi);
        }
    }
}

// ---------------- launch ----------------
extern "C" void kernel_launch(void* const* d_in, const int* in_sizes, int n_in,
                              void* d_out, int out_size) {
    const float* user = (const float*)d_in[0];
    const float* item = (const float*)d_in[1];
    const float* W    = (const float*)d_in[2];
    const int*   hix  = (const int*)d_in[3];
    const int*   tix  = (const int*)d_in[4];
    const int n_edges = in_sizes[3];
    float* out = (float*)d_out;

    cudaFuncSetAttribute(fused_layer_kernel,
                         cudaFuncAttributeMaxDynamicSharedMemorySize, SMEM_FL);

    float *A, *B;
    __half *S0, *S1;
    void *degp, *statep;
    cudaGetSymbolAddress((void**)&A, g_embA);
    cudaGetSymbolAddress((void**)&B, g_embB);
    cudaGetSymbolAddress((void**)&S0, g_embS0);
    cudaGetSymbolAddress((void**)&S1, g_embS1);
    cudaGetSymbolAddress(&degp, g_deg);
    cudaGetSymbolAddress(&statep, g_state);

    const int TB = 256;
    cudaMemsetAsync(degp, 0, N_NODES * sizeof(int));
    cudaMemsetAsync(statep, 0, NBLK * sizeof(unsigned long long));

    hist_kernel<<<4096, TB>>>(hix, n_edges);                               // kernel 1
    scan_kernel<<<NBLK, 1024>>>(n_edges);                                  // kernel 2
    scatter_init_kernel<<<4096, TB>>>(hix, tix, n_edges, user, item, A, out, S0); // kernel 3

    const int tile_blocks = (N_NODES + 127) / 128;

    // layer 0: reads A + S0; writes B (new emb), out, S1
    fused_layer_kernel<<<tile_blocks, TB, SMEM_FL>>>(A, S0, W, B, out, S1); // kernel 4 (profiled)
    // layer 1: reads B + S1; writes out only
    fused_layer_kernel<<<tile_blocks, TB, SMEM_FL>>>(B, S1, W, nullptr, out, nullptr);
}

// round 14
// speedup vs baseline: 1.0297x; 1.0297x over previous
#include <cuda_runtime.h>
#include <cuda_fp16.h>
#include <math.h>
#include <cstdint>

#define N_USERS 100000
#define N_ITEMS 50000
#define N_NODES 150000
#define EMB 64
#define NINT 128
#define MAX_EDGES 4000000

#define N4 ((N_NODES + 3) / 4)
#define NBLK ((N4 + 1023) / 1024)

// ---------------- static device scratch ----------------
__device__ int    g_deg[N_NODES];
__device__ float  g_dis[N_NODES];
__device__ int    g_rowptr[N_NODES + 1];
__device__ int    g_cursor[N_NODES];
__device__ int    g_ecol[MAX_EDGES];
__device__ volatile unsigned long long g_state[NBLK];
__device__ float  g_embA[(size_t)N_NODES * EMB];
__device__ float  g_embB[(size_t)N_NODES * EMB];
__device__ float  g_gnn [(size_t)N_NODES * EMB];   // spmm output buffer
__device__ __half g_embS0[(size_t)N_NODES * EMB];
__device__ __half g_embS1[(size_t)N_NODES * EMB];
__device__ __align__(16) __half g_WTh[128 * 72];   // W^T staged fp16 (padded)
__device__ __align__(16) __half g_W2h[64 * 136];   // W   staged fp16 (padded)

// ---------------- packed fp32x2 helpers ----------------
__device__ __forceinline__ unsigned long long fma2(unsigned long long a,
                                                   unsigned long long b,
                                                   unsigned long long c) {
    unsigned long long d;
    asm("fma.rn.f32x2 %0, %1, %2, %3;" : "=l"(d) : "l"(a), "l"(b), "l"(c));
    return d;
}
__device__ __forceinline__ unsigned long long pk2(float x, float y) {
    unsigned long long r;
    asm("mov.b64 %0, {%1, %2};" : "=l"(r) : "f"(x), "f"(y));
    return r;
}
__device__ __forceinline__ float2 upk(unsigned long long v) {
    float2 f;
    asm("mov.b64 {%0, %1}, %2;" : "=f"(f.x), "=f"(f.y) : "l"(v));
    return f;
}
__device__ __forceinline__ unsigned long long h2f2(unsigned int h) {
    float2 f = __half22float2(*(const __half2*)&h);
    return pk2(f.x, f.y);
}

// ---------------- precompute ----------------
__global__ void hist_kernel(const int* __restrict__ h, int n) {
    int stride = gridDim.x * blockDim.x;
    for (int i = blockIdx.x * blockDim.x + threadIdx.x; i < n; i += stride)
        atomicAdd(&g_deg[h[i]], 1);
}

__global__ __launch_bounds__(1024) void scan_kernel(int n_edges) {
    __shared__ int ws[32];
    __shared__ int s_excl;
    const int t = threadIdx.x, b = blockIdx.x;
    const int lane = t & 31, wid = t >> 5;
    const int idx = b * 1024 + t;
    int4 v = (idx < N4) ? ((const int4*)g_deg)[idx] : make_int4(0, 0, 0, 0);
    int s = v.x + v.y + v.z + v.w;
    int x = s;
    #pragma unroll
    for (int o = 1; o < 32; o <<= 1) {
        int y = __shfl_up_sync(0xffffffffu, x, o);
        if (lane >= o) x += y;
    }
    if (lane == 31) ws[wid] = x;
    __syncthreads();
    if (wid == 0) {
        int z = ws[lane];
        #pragma unroll
        for (int o = 1; o < 32; o <<= 1) {
            int y = __shfl_up_sync(0xffffffffu, z, o);
            if (lane >= o) z += y;
        }
        ws[lane] = z;
    }
    __syncthreads();
    const int total = ws[31];

    if (t == 0) {
        if (b == 0) {
            g_state[0] = (2ull << 32) | (unsigned)total;
            s_excl = 0;
        } else {
            g_state[b] = (1ull << 32) | (unsigned)total;
            int excl = 0;
            int p = b - 1;
            while (true) {
                unsigned long long st;
                do { st = g_state[p]; } while ((st >> 32) == 0ull);
                excl += (int)(unsigned)st;
                if ((st >> 32) == 2ull) break;
                p--;
            }
            g_state[b] = (2ull << 32) | (unsigned)(excl + total);
            s_excl = excl;
        }
    }
    __syncthreads();

    int base = s_excl + ((wid > 0) ? ws[wid - 1] : 0) + (x - s);
    if (idx < N4) {
        int i = idx * 4;
        int e0 = base, e1 = e0 + v.x, e2 = e1 + v.y, e3 = e2 + v.z;
        g_rowptr[i + 0] = e0; g_cursor[i + 0] = e0;
        g_rowptr[i + 1] = e1; g_cursor[i + 1] = e1;
        g_rowptr[i + 2] = e2; g_cursor[i + 2] = e2;
        g_rowptr[i + 3] = e3; g_cursor[i + 3] = e3;
        g_dis[i + 0] = (v.x > 0) ? rsqrtf((float)v.x) : 0.0f;
        g_dis[i + 1] = (v.y > 0) ? rsqrtf((float)v.y) : 0.0f;
        g_dis[i + 2] = (v.z > 0) ? rsqrtf((float)v.z) : 0.0f;
        g_dis[i + 3] = (v.w > 0) ? rsqrtf((float)v.w) : 0.0f;
    }
    if (b == 0 && t == 0) g_rowptr[N_NODES] = n_edges;
}

// fused: CSR scatter + embA/S0 init + fp16 W staging (no out write)
__global__ void scatter_init_kernel(const int* __restrict__ h, const int* __restrict__ t,
                                    int n, const float* __restrict__ W,
                                    const float* __restrict__ u, const float* __restrict__ it,
                                    float* __restrict__ embA, __half* __restrict__ S) {
    const int stride = gridDim.x * blockDim.x;
    const int tid0 = blockIdx.x * blockDim.x + threadIdx.x;
    const int total4 = N_NODES * EMB / 4;
    const int ub4 = N_USERS * EMB / 4;
    for (int i = tid0; i < total4; i += stride) {
        float4 v = (i < ub4) ? ((const float4*)u)[i] : ((const float4*)it)[i - ub4];
        ((float4*)embA)[i] = v;
        float d = g_dis[i >> 4];
        ((__half2*)S)[i * 2 + 0] = __floats2half2_rn(v.x * d, v.y * d);
        ((__half2*)S)[i * 2 + 1] = __floats2half2_rn(v.z * d, v.w * d);
    }
    for (int i = tid0; i < 64 * 128; i += stride) {
        int d = i >> 7, j = i & 127;
        __half hh = __float2half(W[i]);
        g_WTh[j * 72 + d] = hh;
        g_W2h[d * 136 + j] = hh;
    }
    for (int i = tid0; i < n; i += stride) {
        int hh = h[i];
        int pos = atomicAdd(&g_cursor[hh], 1);
        g_ecol[pos] = t[i];
    }
}

// ---------------- SPMM: warp/node, fp16 rows, 8 lanes/row, pipelined ----------------
__global__ __launch_bounds__(256) void spmm_kernel(const __half* __restrict__ S,
                                                   float* __restrict__ xout) {
    const int lane = threadIdx.x & 31;
    const int grp = lane >> 3;
    const int q = lane & 7;
    const int n = (blockIdx.x << 3) + (threadIdx.x >> 5);
    if (n >= N_NODES) return;
    const int beg = g_rowptr[n], end = g_rowptr[n + 1];
    const uint4* S4 = (const uint4*)S;

    unsigned long long a0 = 0ull, a1 = 0ull, a2 = 0ull, a3 = 0ull;
    const unsigned long long one2 = 0x3f8000003f800000ull;
    int j = beg;
    const int nq = (end - beg) >> 2;

    if (nq > 0) {
        int c = g_ecol[j + grp];
        uint4 v = S4[(size_t)c * 8 + q];
        for (int b = 1; b < nq; b++) {
            j += 4;
            int d = g_ecol[j + grp];
            uint4 w = S4[(size_t)d * 8 + q];
            a0 = fma2(h2f2(v.x), one2, a0);
            a1 = fma2(h2f2(v.y), one2, a1);
            a2 = fma2(h2f2(v.z), one2, a2);
            a3 = fma2(h2f2(v.w), one2, a3);
            v = w;
        }
        a0 = fma2(h2f2(v.x), one2, a0);
        a1 = fma2(h2f2(v.y), one2, a1);
        a2 = fma2(h2f2(v.z), one2, a2);
        a3 = fma2(h2f2(v.w), one2, a3);
        j += 4;
    }

    if (j + grp < end) {
        int c = g_ecol[j + grp];
        uint4 v = S4[(size_t)c * 8 + q];
        a0 = fma2(h2f2(v.x), one2, a0);
        a1 = fma2(h2f2(v.y), one2, a1);
        a2 = fma2(h2f2(v.z), one2, a2);
        a3 = fma2(h2f2(v.w), one2, a3);
    }

    float2 f0 = upk(a0), f1 = upk(a1), f2 = upk(a2), f3 = upk(a3);
    #pragma unroll
    for (int o = 8; o <= 16; o <<= 1) {
        f0.x += __shfl_xor_sync(0xffffffffu, f0.x, o);
        f0.y += __shfl_xor_sync(0xffffffffu, f0.y, o);
        f1.x += __shfl_xor_sync(0xffffffffu, f1.x, o);
        f1.y += __shfl_xor_sync(0xffffffffu, f1.y, o);
        f2.x += __shfl_xor_sync(0xffffffffu, f2.x, o);
        f2.y += __shfl_xor_sync(0xffffffffu, f2.y, o);
        f3.x += __shfl_xor_sync(0xffffffffu, f3.x, o);
        f3.y += __shfl_xor_sync(0xffffffffu, f3.y, o);
    }

    if (grp == 0) {
        float dn = g_dis[n];
        float* row = xout + (size_t)n * EMB + q * 8;
        *(float4*)(row)     = make_float4(f0.x * dn, f0.y * dn, f1.x * dn, f1.y * dn);
        *(float4*)(row + 4) = make_float4(f2.x * dn, f2.y * dn, f3.x * dn, f3.y * dn);
    }
}

// ================ mma.sync fp16 intent kernel (split, lean staging) ================
#define OFF_WT 0               // W^T [128j][72d] fp16 = 18432 B
#define OFF_W2 18432           // W   [64d][136j] fp16 = 17408 B
#define OFF_X  35840           // X   [128m][72d] fp16 = 18432 B
#define SMEM_MMA 54272
#define WTLDB 144
#define W2LDB 272
#define XLDB  144

__device__ __forceinline__ uint32_t pack_h2(float x, float y) {
    __half2 h = __floats2half2_rn(x, y);
    return *(uint32_t*)&h;
}
__device__ __forceinline__ void ldmx4(uint32_t addr, uint32_t& r0, uint32_t& r1,
                                      uint32_t& r2, uint32_t& r3) {
    asm volatile("ldmatrix.sync.aligned.m8n8.x4.shared.b16 {%0,%1,%2,%3}, [%4];"
                 : "=r"(r0), "=r"(r1), "=r"(r2), "=r"(r3) : "r"(addr));
}
__device__ __forceinline__ void ldmx2(uint32_t addr, uint32_t& r0, uint32_t& r1) {
    asm volatile("ldmatrix.sync.aligned.m8n8.x2.shared.b16 {%0,%1}, [%2];"
                 : "=r"(r0), "=r"(r1) : "r"(addr));
}
__device__ __forceinline__ void mma16816(float& c0, float& c1, float& c2, float& c3,
                                         uint32_t a0, uint32_t a1, uint32_t a2, uint32_t a3,
                                         uint32_t b0, uint32_t b1) {
    asm volatile("mma.sync.aligned.m16n8k16.row.col.f32.f16.f16.f32 "
                 "{%0,%1,%2,%3}, {%4,%5,%6,%7}, {%8,%9}, {%0,%1,%2,%3};"
                 : "+f"(c0), "+f"(c1), "+f"(c2), "+f"(c3)
                 : "r"(a0), "r"(a1), "r"(a2), "r"(a3), "r"(b0), "r"(b1));
}

// epilogue modes:
//   layer0: emb_out = gnn + Y; Sout = half(dis * emb_out)          (no out)
//   layer1: out = (a0row + xinrow + (gnn + Y)) / 3                  (a0 != null)
__global__ __launch_bounds__(256, 2) void intent_mma_kernel(
    const float* __restrict__ xin, const float* __restrict__ gnn,
    float* __restrict__ emb_out, __half* __restrict__ Sout,
    const float* __restrict__ a0row, float* __restrict__ out) {
    extern __shared__ char smem[];
    __half* hX = (__half*)(smem + OFF_X);
    const uint32_t sb = (uint32_t)__cvta_generic_to_shared(smem);

    const int tid = threadIdx.x;
    const int w = tid >> 5, lane = tid & 31;
    const int node0 = blockIdx.x * 128;

    // ---- stage W^T and W via vector copy of pre-converted fp16 ----
    {
        const uint4* src = (const uint4*)g_WTh;
        uint4* dst = (uint4*)(smem + OFF_WT);
        for (int i = tid; i < 1152; i += 256) dst[i] = src[i];
        const uint4* src2 = (const uint4*)g_W2h;
        uint4* dst2 = (uint4*)(smem + OFF_W2);
        for (int i = tid; i < 1088; i += 256) dst2[i] = src2[i];
    }
    // ---- stage X (fp32 -> fp16) ----
    for (int i2 = tid; i2 < 128 * 32; i2 += 256) {
        int m = i2 >> 5, d2 = i2 & 31;
        int nd = node0 + m;
        float2 v = (nd < N_NODES) ? *(const float2*)(xin + (size_t)nd * EMB + d2 * 2)
                                  : make_float2(0.f, 0.f);
        ((__half2*)hX)[m * 36 + d2] = __floats2half2_rn(v.x, v.y);
    }
    __syncthreads();

    // ---- phase 1: warp w owns rows m0..m0+16; logits acc[16][4] ----
    const int m0 = w * 16;
    float acc[16][4];
    #pragma unroll
    for (int n = 0; n < 16; n++) {
        acc[n][0] = 0.f; acc[n][1] = 0.f; acc[n][2] = 0.f; acc[n][3] = 0.f;
    }
    const uint32_t xrow = (uint32_t)(m0 + (lane & 7) + 8 * ((lane >> 3) & 1));
    const uint32_t xaddr0 = sb + OFF_X + xrow * XLDB + (uint32_t)(lane >> 4) * 16;
    const uint32_t brow_in = (uint32_t)(lane & 7);
    const uint32_t bmat = (uint32_t)((lane >> 3) & 1) * 16;

    #pragma unroll
    for (int kf = 0; kf < 4; kf++) {
        uint32_t a0f, a1f, a2f, a3f;
        ldmx4(xaddr0 + kf * 32, a0f, a1f, a2f, a3f);
        #pragma unroll
        for (int n = 0; n < 16; n++) {
            uint32_t b0, b1;
            uint32_t baddr = sb + OFF_WT + (n * 8 + brow_in) * WTLDB + kf * 32 + bmat;
            ldmx2(baddr, b0, b1);
            mma16816(acc[n][0], acc[n][1], acc[n][2], acc[n][3], a0f, a1f, a2f, a3f, b0, b1);
        }
    }

    // ---- softmax in registers ----
    float mx_lo = -1e30f, mx_hi = -1e30f;
    #pragma unroll
    for (int n = 0; n < 16; n++) {
        mx_lo = fmaxf(mx_lo, fmaxf(acc[n][0], acc[n][1]));
        mx_hi = fmaxf(mx_hi, fmaxf(acc[n][2], acc[n][3]));
    }
    mx_lo = fmaxf(mx_lo, __shfl_xor_sync(0xffffffffu, mx_lo, 1));
    mx_lo = fmaxf(mx_lo, __shfl_xor_sync(0xffffffffu, mx_lo, 2));
    mx_hi = fmaxf(mx_hi, __shfl_xor_sync(0xffffffffu, mx_hi, 1));
    mx_hi = fmaxf(mx_hi, __shfl_xor_sync(0xffffffffu, mx_hi, 2));
    float s_lo = 0.f, s_hi = 0.f;
    #pragma unroll
    for (int n = 0; n < 16; n++) {
        acc[n][0] = __expf(acc[n][0] - mx_lo); s_lo += acc[n][0];
        acc[n][1] = __expf(acc[n][1] - mx_lo); s_lo += acc[n][1];
        acc[n][2] = __expf(acc[n][2] - mx_hi); s_hi += acc[n][2];
        acc[n][3] = __expf(acc[n][3] - mx_hi); s_hi += acc[n][3];
    }
    s_lo += __shfl_xor_sync(0xffffffffu, s_lo, 1);
    s_lo += __shfl_xor_sync(0xffffffffu, s_lo, 2);
    s_hi += __shfl_xor_sync(0xffffffffu, s_hi, 1);
    s_hi += __shfl_xor_sync(0xffffffffu, s_hi, 2);
    const float inv_lo = 1.0f / s_lo, inv_hi = 1.0f / s_hi;

    // ---- repack scaled accs directly as phase2 A fragments ----
    uint32_t A2[8][4];
    #pragma unroll
    for (int kf2 = 0; kf2 < 8; kf2++) {
        A2[kf2][0] = pack_h2(acc[2 * kf2][0] * inv_lo,     acc[2 * kf2][1] * inv_lo);
        A2[kf2][1] = pack_h2(acc[2 * kf2][2] * inv_hi,     acc[2 * kf2][3] * inv_hi);
        A2[kf2][2] = pack_h2(acc[2 * kf2 + 1][0] * inv_lo, acc[2 * kf2 + 1][1] * inv_lo);
        A2[kf2][3] = pack_h2(acc[2 * kf2 + 1][2] * inv_hi, acc[2 * kf2 + 1][3] * inv_hi);
    }

    // ---- phase 2: Y = P @ W^T ----
    float acc2[8][4];
    #pragma unroll
    for (int n2 = 0; n2 < 8; n2++) {
        acc2[n2][0] = 0.f; acc2[n2][1] = 0.f; acc2[n2][2] = 0.f; acc2[n2][3] = 0.f;
    }
    #pragma unroll
    for (int kf2 = 0; kf2 < 8; kf2++) {
        #pragma unroll
        for (int n2 = 0; n2 < 8; n2++) {
            uint32_t b0, b1;
            uint32_t baddr = sb + OFF_W2 + (n2 * 8 + brow_in) * W2LDB + kf2 * 32 + bmat;
            ldmx2(baddr, b0, b1);
            mma16816(acc2[n2][0], acc2[n2][1], acc2[n2][2], acc2[n2][3],
                     A2[kf2][0], A2[kf2][1], A2[kf2][2], A2[kf2][3], b0, b1);
        }
    }

    // ---- epilogue ----
    const float third = 1.0f / 3.0f;
    const int r_lo = node0 + m0 + (lane >> 2);
    const int r_hi = r_lo + 8;
    const int q2 = (lane & 3) * 2;
    const float d_lo = (Sout && r_lo < N_NODES) ? g_dis[r_lo] : 0.0f;
    const float d_hi = (Sout && r_hi < N_NODES) ? g_dis[r_hi] : 0.0f;
    #pragma unroll
    for (int n2 = 0; n2 < 8; n2++) {
        int dcol = n2 * 8 + q2;
        if (r_lo < N_NODES) {
            size_t idx = (size_t)r_lo * EMB + dcol;
            float2 g = *(const float2*)(gnn + idx);
            float y0 = acc2[n2][0] + g.x, y1 = acc2[n2][1] + g.y;
            if (emb_out) *(float2*)(emb_out + idx) = make_float2(y0, y1);
            if (Sout) *(__half2*)(Sout + idx) = __floats2half2_rn(y0 * d_lo, y1 * d_lo);
            if (out) {
                float2 a = *(const float2*)(a0row + idx);
                float2 b = *(const float2*)(xin + idx);
                *(float2*)(out + idx) = make_float2((a.x + b.x + y0) * third,
                                                    (a.y + b.y + y1) * third);
            }
        }
        if (r_hi < N_NODES) {
            size_t idx = (size_t)r_hi * EMB + dcol;
            float2 g = *(const float2*)(gnn + idx);
            float y0 = acc2[n2][2] + g.x, y1 = acc2[n2][3] + g.y;
            if (emb_out) *(float2*)(emb_out + idx) = make_float2(y0, y1);
            if (Sout) *(__half2*)(Sout + idx) = __floats2half2_rn(y0 * d_hi, y1 * d_hi);
            if (out) {
                float2 a = *(const float2*)(a0row + idx);
                float2 b = *(const float2*)(xin + idx);
                *(float2*)(out + idx) = make_float2((a.x + b.x + y0) * third,
                                                    (a.y + b.y + y1) * third);
            }
        }
    }
}

// ---------------- launch ----------------
extern "C" void kernel_launch(void* const* d_in, const int* in_sizes, int n_in,
                              void* d_out, int out_size) {
    const float* user = (const float*)d_in[0];
    const float* item = (const float*)d_in[1];
    const float* W    = (const float*)d_in[2];
    const int*   hix  = (const int*)d_in[3];
    const int*   tix  = (const int*)d_in[4];
    const int n_edges = in_sizes[3];
    float* out = (float*)d_out;

    cudaFuncSetAttribute(intent_mma_kernel,
                         cudaFuncAttributeMaxDynamicSharedMemorySize, SMEM_MMA);

    float *A, *B, *G;
    __half *S0, *S1;
    void *degp, *statep;
    cudaGetSymbolAddress((void**)&A, g_embA);
    cudaGetSymbolAddress((void**)&B, g_embB);
    cudaGetSymbolAddress((void**)&G, g_gnn);
    cudaGetSymbolAddress((void**)&S0, g_embS0);
    cudaGetSymbolAddress((void**)&S1, g_embS1);
    cudaGetSymbolAddress(&degp, g_deg);
    cudaGetSymbolAddress(&statep, g_state);

    const int TB = 256;
    cudaMemsetAsync(degp, 0, N_NODES * sizeof(int));
    cudaMemsetAsync(statep, 0, NBLK * sizeof(unsigned long long));

    hist_kernel<<<4096, TB>>>(hix, n_edges);                               // kernel 1
    scan_kernel<<<NBLK, 1024>>>(n_edges);                                  // kernel 2
    scatter_init_kernel<<<4096, TB>>>(hix, tix, n_edges, W, user, item, A, S0); // kernel 3

    const int spmm_blocks = (N_NODES + 7) / 8;
    const int tile_blocks = (N_NODES + 127) / 128;

    // layer 0
    spmm_kernel<<<spmm_blocks, TB>>>(S0, G);                               // kernel 4 (profiled)
    intent_mma_kernel<<<tile_blocks, TB, SMEM_MMA>>>(A, G, B, S1, nullptr, nullptr);
    // layer 1
    spmm_kernel<<<spmm_blocks, TB>>>(S1, G);
    intent_mma_kernel<<<tile_blocks, TB, SMEM_MMA>>>(B, G, nullptr, nullptr, A, out);
}

// round 15
// speedup vs baseline: 1.3867x; 1.3467x over previous
#include <cuda_runtime.h>
#include <cuda_fp16.h>
#include <math.h>
#include <cstdint>

#define N_USERS 100000
#define N_ITEMS 50000
#define N_NODES 150000
#define EMB 64
#define NINT 128
#define MAX_EDGES 4000000

#define N4 ((N_NODES + 3) / 4)
#define NBLK ((N4 + 1023) / 1024)

// ---------------- static device scratch (all 256B-aligned: gathered rows must not straddle lines) ----------------
__device__ __align__(256) int    g_deg[N_NODES];
__device__ __align__(256) float  g_dis[N_NODES];
__device__ __align__(256) int    g_rowptr[N_NODES + 1];
__device__ __align__(256) int    g_cursor[N_NODES];
__device__ __align__(256) int    g_ecol[MAX_EDGES];
__device__ __align__(256) volatile unsigned long long g_state[NBLK];
__device__ __align__(256) float  g_embA[(size_t)N_NODES * EMB];
__device__ __align__(256) float  g_embB[(size_t)N_NODES * EMB];
__device__ __align__(256) float  g_gnn [(size_t)N_NODES * EMB];   // spmm output buffer
__device__ __align__(256) __half g_embS0[(size_t)N_NODES * EMB];
__device__ __align__(256) __half g_embS1[(size_t)N_NODES * EMB];
__device__ __align__(256) __half g_WTh[128 * 72];   // W^T staged fp16 (padded)
__device__ __align__(256) __half g_W2h[64 * 136];   // W   staged fp16 (padded)

// ---------------- packed fp32x2 helpers ----------------
__device__ __forceinline__ unsigned long long fma2(unsigned long long a,
                                                   unsigned long long b,
                                                   unsigned long long c) {
    unsigned long long d;
    asm("fma.rn.f32x2 %0, %1, %2, %3;" : "=l"(d) : "l"(a), "l"(b), "l"(c));
    return d;
}
__device__ __forceinline__ unsigned long long pk2(float x, float y) {
    unsigned long long r;
    asm("mov.b64 %0, {%1, %2};" : "=l"(r) : "f"(x), "f"(y));
    return r;
}
__device__ __forceinline__ float2 upk(unsigned long long v) {
    float2 f;
    asm("mov.b64 {%0, %1}, %2;" : "=f"(f.x), "=f"(f.y) : "l"(v));
    return f;
}
__device__ __forceinline__ unsigned long long h2f2(unsigned int h) {
    float2 f = __half22float2(*(const __half2*)&h);
    return pk2(f.x, f.y);
}

// ---------------- precompute ----------------
__global__ void hist_kernel(const int* __restrict__ h, int n) {
    int stride = gridDim.x * blockDim.x;
    for (int i = blockIdx.x * blockDim.x + threadIdx.x; i < n; i += stride)
        atomicAdd(&g_deg[h[i]], 1);
}

__global__ __launch_bounds__(1024) void scan_kernel(int n_edges) {
    __shared__ int ws[32];
    __shared__ int s_excl;
    const int t = threadIdx.x, b = blockIdx.x;
    const int lane = t & 31, wid = t >> 5;
    const int idx = b * 1024 + t;
    int4 v = (idx < N4) ? ((const int4*)g_deg)[idx] : make_int4(0, 0, 0, 0);
    int s = v.x + v.y + v.z + v.w;
    int x = s;
    #pragma unroll
    for (int o = 1; o < 32; o <<= 1) {
        int y = __shfl_up_sync(0xffffffffu, x, o);
        if (lane >= o) x += y;
    }
    if (lane == 31) ws[wid] = x;
    __syncthreads();
    if (wid == 0) {
        int z = ws[lane];
        #pragma unroll
        for (int o = 1; o < 32; o <<= 1) {
            int y = __shfl_up_sync(0xffffffffu, z, o);
            if (lane >= o) z += y;
        }
        ws[lane] = z;
    }
    __syncthreads();
    const int total = ws[31];

    if (t == 0) {
        if (b == 0) {
            g_state[0] = (2ull << 32) | (unsigned)total;
            s_excl = 0;
        } else {
            g_state[b] = (1ull << 32) | (unsigned)total;
            int excl = 0;
            int p = b - 1;
            while (true) {
                unsigned long long st;
                do { st = g_state[p]; } while ((st >> 32) == 0ull);
                excl += (int)(unsigned)st;
                if ((st >> 32) == 2ull) break;
                p--;
            }
            g_state[b] = (2ull << 32) | (unsigned)(excl + total);
            s_excl = excl;
        }
    }
    __syncthreads();

    int base = s_excl + ((wid > 0) ? ws[wid - 1] : 0) + (x - s);
    if (idx < N4) {
        int i = idx * 4;
        int e0 = base, e1 = e0 + v.x, e2 = e1 + v.y, e3 = e2 + v.z;
        g_rowptr[i + 0] = e0; g_cursor[i + 0] = e0;
        g_rowptr[i + 1] = e1; g_cursor[i + 1] = e1;
        g_rowptr[i + 2] = e2; g_cursor[i + 2] = e2;
        g_rowptr[i + 3] = e3; g_cursor[i + 3] = e3;
        g_dis[i + 0] = (v.x > 0) ? rsqrtf((float)v.x) : 0.0f;
        g_dis[i + 1] = (v.y > 0) ? rsqrtf((float)v.y) : 0.0f;
        g_dis[i + 2] = (v.z > 0) ? rsqrtf((float)v.z) : 0.0f;
        g_dis[i + 3] = (v.w > 0) ? rsqrtf((float)v.w) : 0.0f;
    }
    if (b == 0 && t == 0) g_rowptr[N_NODES] = n_edges;
}

// fused: CSR scatter + embA/S0 init + fp16 W staging
__global__ void scatter_init_kernel(const int* __restrict__ h, const int* __restrict__ t,
                                    int n, const float* __restrict__ W,
                                    const float* __restrict__ u, const float* __restrict__ it,
                                    float* __restrict__ embA, __half* __restrict__ S) {
    const int stride = gridDim.x * blockDim.x;
    const int tid0 = blockIdx.x * blockDim.x + threadIdx.x;
    const int total4 = N_NODES * EMB / 4;
    const int ub4 = N_USERS * EMB / 4;
    for (int i = tid0; i < total4; i += stride) {
        float4 v = (i < ub4) ? ((const float4*)u)[i] : ((const float4*)it)[i - ub4];
        ((float4*)embA)[i] = v;
        float d = g_dis[i >> 4];
        ((__half2*)S)[i * 2 + 0] = __floats2half2_rn(v.x * d, v.y * d);
        ((__half2*)S)[i * 2 + 1] = __floats2half2_rn(v.z * d, v.w * d);
    }
    for (int i = tid0; i < 64 * 128; i += stride) {
        int d = i >> 7, j = i & 127;
        __half hh = __float2half(W[i]);
        g_WTh[j * 72 + d] = hh;
        g_W2h[d * 136 + j] = hh;
    }
    for (int i = tid0; i < n; i += stride) {
        int hh = h[i];
        int pos = atomicAdd(&g_cursor[hh], 1);
        g_ecol[pos] = t[i];
    }
}

// ---------------- SPMM: warp/node, fp16 rows, 8 lanes/row, pipelined ----------------
__global__ __launch_bounds__(256) void spmm_kernel(const __half* __restrict__ S,
                                                   float* __restrict__ xout) {
    const int lane = threadIdx.x & 31;
    const int grp = lane >> 3;
    const int q = lane & 7;
    const int n = (blockIdx.x << 3) + (threadIdx.x >> 5);
    if (n >= N_NODES) return;
    const int beg = g_rowptr[n], end = g_rowptr[n + 1];
    const uint4* S4 = (const uint4*)S;

    unsigned long long a0 = 0ull, a1 = 0ull, a2 = 0ull, a3 = 0ull;
    const unsigned long long one2 = 0x3f8000003f800000ull;
    int j = beg;
    const int nq = (end - beg) >> 2;

    if (nq > 0) {
        int c = g_ecol[j + grp];
        uint4 v = S4[(size_t)c * 8 + q];
        for (int b = 1; b < nq; b++) {
            j += 4;
            int d = g_ecol[j + grp];
            uint4 w = S4[(size_t)d * 8 + q];
            a0 = fma2(h2f2(v.x), one2, a0);
            a1 = fma2(h2f2(v.y), one2, a1);
            a2 = fma2(h2f2(v.z), one2, a2);
            a3 = fma2(h2f2(v.w), one2, a3);
            v = w;
        }
        a0 = fma2(h2f2(v.x), one2, a0);
        a1 = fma2(h2f2(v.y), one2, a1);
        a2 = fma2(h2f2(v.z), one2, a2);
        a3 = fma2(h2f2(v.w), one2, a3);
        j += 4;
    }

    if (j + grp < end) {
        int c = g_ecol[j + grp];
        uint4 v = S4[(size_t)c * 8 + q];
        a0 = fma2(h2f2(v.x), one2, a0);
        a1 = fma2(h2f2(v.y), one2, a1);
        a2 = fma2(h2f2(v.z), one2, a2);
        a3 = fma2(h2f2(v.w), one2, a3);
    }

    float2 f0 = upk(a0), f1 = upk(a1), f2 = upk(a2), f3 = upk(a3);
    #pragma unroll
    for (int o = 8; o <= 16; o <<= 1) {
        f0.x += __shfl_xor_sync(0xffffffffu, f0.x, o);
        f0.y += __shfl_xor_sync(0xffffffffu, f0.y, o);
        f1.x += __shfl_xor_sync(0xffffffffu, f1.x, o);
        f1.y += __shfl_xor_sync(0xffffffffu, f1.y, o);
        f2.x += __shfl_xor_sync(0xffffffffu, f2.x, o);
        f2.y += __shfl_xor_sync(0xffffffffu, f2.y, o);
        f3.x += __shfl_xor_sync(0xffffffffu, f3.x, o);
        f3.y += __shfl_xor_sync(0xffffffffu, f3.y, o);
    }

    if (grp == 0) {
        float dn = g_dis[n];
        float* row = xout + (size_t)n * EMB + q * 8;
        *(float4*)(row)     = make_float4(f0.x * dn, f0.y * dn, f1.x * dn, f1.y * dn);
        *(float4*)(row + 4) = make_float4(f2.x * dn, f2.y * dn, f3.x * dn, f3.y * dn);
    }
}

// ================ mma.sync fp16 intent kernel (split, lean staging) ================
#define OFF_WT 0               // W^T [128j][72d] fp16 = 18432 B
#define OFF_W2 18432           // W   [64d][136j] fp16 = 17408 B
#define OFF_X  35840           // X   [128m][72d] fp16 = 18432 B
#define SMEM_MMA 54272
#define WTLDB 144
#define W2LDB 272
#define XLDB  144

__device__ __forceinline__ uint32_t pack_h2(float x, float y) {
    __half2 h = __floats2half2_rn(x, y);
    return *(uint32_t*)&h;
}
__device__ __forceinline__ void ldmx4(uint32_t addr, uint32_t& r0, uint32_t& r1,
                                      uint32_t& r2, uint32_t& r3) {
    asm volatile("ldmatrix.sync.aligned.m8n8.x4.shared.b16 {%0,%1,%2,%3}, [%4];"
                 : "=r"(r0), "=r"(r1), "=r"(r2), "=r"(r3) : "r"(addr));
}
__device__ __forceinline__ void ldmx2(uint32_t addr, uint32_t& r0, uint32_t& r1) {
    asm volatile("ldmatrix.sync.aligned.m8n8.x2.shared.b16 {%0,%1}, [%2];"
                 : "=r"(r0), "=r"(r1) : "r"(addr));
}
__device__ __forceinline__ void mma16816(float& c0, float& c1, float& c2, float& c3,
                                         uint32_t a0, uint32_t a1, uint32_t a2, uint32_t a3,
                                         uint32_t b0, uint32_t b1) {
    asm volatile("mma.sync.aligned.m16n8k16.row.col.f32.f16.f16.f32 "
                 "{%0,%1,%2,%3}, {%4,%5,%6,%7}, {%8,%9}, {%0,%1,%2,%3};"
                 : "+f"(c0), "+f"(c1), "+f"(c2), "+f"(c3)
                 : "r"(a0), "r"(a1), "r"(a2), "r"(a3), "r"(b0), "r"(b1));
}

// epilogue modes:
//   layer0: emb_out = gnn + Y; Sout = half(dis * emb_out)          (no out)
//   layer1: out = (a0row + xinrow + (gnn + Y)) / 3                  (a0 != null)
__global__ __launch_bounds__(256, 2) void intent_mma_kernel(
    const float* __restrict__ xin, const float* __restrict__ gnn,
    float* __restrict__ emb_out, __half* __restrict__ Sout,
    const float* __restrict__ a0row, float* __restrict__ out) {
    extern __shared__ char smem[];
    __half* hX = (__half*)(smem + OFF_X);
    const uint32_t sb = (uint32_t)__cvta_generic_to_shared(smem);

    const int tid = threadIdx.x;
    const int w = tid >> 5, lane = tid & 31;
    const int node0 = blockIdx.x * 128;

    // ---- stage W^T and W via vector copy of pre-converted fp16 ----
    {
        const uint4* src = (const uint4*)g_WTh;
        uint4* dst = (uint4*)(smem + OFF_WT);
        for (int i = tid; i < 1152; i += 256) dst[i] = src[i];
        const uint4* src2 = (const uint4*)g_W2h;
        uint4* dst2 = (uint4*)(smem + OFF_W2);
        for (int i = tid; i < 1088; i += 256) dst2[i] = src2[i];
    }
    // ---- stage X (fp32 -> fp16) ----
    for (int i2 = tid; i2 < 128 * 32; i2 += 256) {
        int m = i2 >> 5, d2 = i2 & 31;
        int nd = node0 + m;
        float2 v = (nd < N_NODES) ? *(const float2*)(xin + (size_t)nd * EMB + d2 * 2)
                                  : make_float2(0.f, 0.f);
        ((__half2*)hX)[m * 36 + d2] = __floats2half2_rn(v.x, v.y);
    }
    __syncthreads();

    // ---- phase 1: warp w owns rows m0..m0+16; logits acc[16][4] ----
    const int m0 = w * 16;
    float acc[16][4];
    #pragma unroll
    for (int n = 0; n < 16; n++) {
        acc[n][0] = 0.f; acc[n][1] = 0.f; acc[n][2] = 0.f; acc[n][3] = 0.f;
    }
    const uint32_t xrow = (uint32_t)(m0 + (lane & 7) + 8 * ((lane >> 3) & 1));
    const uint32_t xaddr0 = sb + OFF_X + xrow * XLDB + (uint32_t)(lane >> 4) * 16;
    const uint32_t brow_in = (uint32_t)(lane & 7);
    const uint32_t bmat = (uint32_t)((lane >> 3) & 1) * 16;

    #pragma unroll
    for (int kf = 0; kf < 4; kf++) {
        uint32_t a0f, a1f, a2f, a3f;
        ldmx4(xaddr0 + kf * 32, a0f, a1f, a2f, a3f);
        #pragma unroll
        for (int n = 0; n < 16; n++) {
            uint32_t b0, b1;
            uint32_t baddr = sb + OFF_WT + (n * 8 + brow_in) * WTLDB + kf * 32 + bmat;
            ldmx2(baddr, b0, b1);
            mma16816(acc[n][0], acc[n][1], acc[n][2], acc[n][3], a0f, a1f, a2f, a3f, b0, b1);
        }
    }

    // ---- softmax in registers ----
    float mx_lo = -1e30f, mx_hi = -1e30f;
    #pragma unroll
    for (int n = 0; n < 16; n++) {
        mx_lo = fmaxf(mx_lo, fmaxf(acc[n][0], acc[n][1]));
        mx_hi = fmaxf(mx_hi, fmaxf(acc[n][2], acc[n][3]));
    }
    mx_lo = fmaxf(mx_lo, __shfl_xor_sync(0xffffffffu, mx_lo, 1));
    mx_lo = fmaxf(mx_lo, __shfl_xor_sync(0xffffffffu, mx_lo, 2));
    mx_hi = fmaxf(mx_hi, __shfl_xor_sync(0xffffffffu, mx_hi, 1));
    mx_hi = fmaxf(mx_hi, __shfl_xor_sync(0xffffffffu, mx_hi, 2));
    float s_lo = 0.f, s_hi = 0.f;
    #pragma unroll
    for (int n = 0; n < 16; n++) {
        acc[n][0] = __expf(acc[n][0] - mx_lo); s_lo += acc[n][0];
        acc[n][1] = __expf(acc[n][1] - mx_lo); s_lo += acc[n][1];
        acc[n][2] = __expf(acc[n][2] - mx_hi); s_hi += acc[n][2];
        acc[n][3] = __expf(acc[n][3] - mx_hi); s_hi += acc[n][3];
    }
    s_lo += __shfl_xor_sync(0xffffffffu, s_lo, 1);
    s_lo += __shfl_xor_sync(0xffffffffu, s_lo, 2);
    s_hi += __shfl_xor_sync(0xffffffffu, s_hi, 1);
    s_hi += __shfl_xor_sync(0xffffffffu, s_hi, 2);
    const float inv_lo = 1.0f / s_lo, inv_hi = 1.0f / s_hi;

    // ---- repack scaled accs directly as phase2 A fragments ----
    uint32_t A2[8][4];
    #pragma unroll
    for (int kf2 = 0; kf2 < 8; kf2++) {
        A2[kf2][0] = pack_h2(acc[2 * kf2][0] * inv_lo,     acc[2 * kf2][1] * inv_lo);
        A2[kf2][1] = pack_h2(acc[2 * kf2][2] * inv_hi,     acc[2 * kf2][3] * inv_hi);
        A2[kf2][2] = pack_h2(acc[2 * kf2 + 1][0] * inv_lo, acc[2 * kf2 + 1][1] * inv_lo);
        A2[kf2][3] = pack_h2(acc[2 * kf2 + 1][2] * inv_hi, acc[2 * kf2 + 1][3] * inv_hi);
    }

    // ---- phase 2: Y = P @ W^T ----
    float acc2[8][4];
    #pragma unroll
    for (int n2 = 0; n2 < 8; n2++) {
        acc2[n2][0] = 0.f; acc2[n2][1] = 0.f; acc2[n2][2] = 0.f; acc2[n2][3] = 0.f;
    }
    #pragma unroll
    for (int kf2 = 0; kf2 < 8; kf2++) {
        #pragma unroll
        for (int n2 = 0; n2 < 8; n2++) {
            uint32_t b0, b1;
            uint32_t baddr = sb + OFF_W2 + (n2 * 8 + brow_in) * W2LDB + kf2 * 32 + bmat;
            ldmx2(baddr, b0, b1);
            mma16816(acc2[n2][0], acc2[n2][1], acc2[n2][2], acc2[n2][3],
                     A2[kf2][0], A2[kf2][1], A2[kf2][2], A2[kf2][3], b0, b1);
        }
    }

    // ---- epilogue ----
    const float third = 1.0f / 3.0f;
    const int r_lo = node0 + m0 + (lane >> 2);
    const int r_hi = r_lo + 8;
    const int q2 = (lane & 3) * 2;
    const float d_lo = (Sout && r_lo < N_NODES) ? g_dis[r_lo] : 0.0f;
    const float d_hi = (Sout && r_hi < N_NODES) ? g_dis[r_hi] : 0.0f;
    #pragma unroll
    for (int n2 = 0; n2 < 8; n2++) {
        int dcol = n2 * 8 + q2;
        if (r_lo < N_NODES) {
            size_t idx = (size_t)r_lo * EMB + dcol;
            float2 g = *(const float2*)(gnn + idx);
            float y0 = acc2[n2][0] + g.x, y1 = acc2[n2][1] + g.y;
            if (emb_out) *(float2*)(emb_out + idx) = make_float2(y0, y1);
            if (Sout) *(__half2*)(Sout + idx) = __floats2half2_rn(y0 * d_lo, y1 * d_lo);
            if (out) {
                float2 a = *(const float2*)(a0row + idx);
                float2 b = *(const float2*)(xin + idx);
                *(float2*)(out + idx) = make_float2((a.x + b.x + y0) * third,
                                                    (a.y + b.y + y1) * third);
            }
        }
        if (r_hi < N_NODES) {
            size_t idx = (size_t)r_hi * EMB + dcol;
            float2 g = *(const float2*)(gnn + idx);
            float y0 = acc2[n2][2] + g.x, y1 = acc2[n2][3] + g.y;
            if (emb_out) *(float2*)(emb_out + idx) = make_float2(y0, y1);
            if (Sout) *(__half2*)(Sout + idx) = __floats2half2_rn(y0 * d_hi, y1 * d_hi);
            if (out) {
                float2 a = *(const float2*)(a0row + idx);
                float2 b = *(const float2*)(xin + idx);
                *(float2*)(out + idx) = make_float2((a.x + b.x + y0) * third,
                                                    (a.y + b.y + y1) * third);
            }
        }
    }
}

// ---------------- launch ----------------
extern "C" void kernel_launch(void* const* d_in, const int* in_sizes, int n_in,
                              void* d_out, int out_size) {
    const float* user = (const float*)d_in[0];
    const float* item = (const float*)d_in[1];
    const float* W    = (const float*)d_in[2];
    const int*   hix  = (const int*)d_in[3];
    const int*   tix  = (const int*)d_in[4];
    const int n_edges = in_sizes[3];
    float* out = (float*)d_out;

    cudaFuncSetAttribute(intent_mma_kernel,
                         cudaFuncAttributeMaxDynamicSharedMemorySize, SMEM_MMA);

    float *A, *B, *G;
    __half *S0, *S1;
    void *degp, *statep;
    cudaGetSymbolAddress((void**)&A, g_embA);
    cudaGetSymbolAddress((void**)&B, g_embB);
    cudaGetSymbolAddress((void**)&G, g_gnn);
    cudaGetSymbolAddress((void**)&S0, g_embS0);
    cudaGetSymbolAddress((void**)&S1, g_embS1);
    cudaGetSymbolAddress(&degp, g_deg);
    cudaGetSymbolAddress(&statep, g_state);

    const int TB = 256;
    cudaMemsetAsync(degp, 0, N_NODES * sizeof(int));
    cudaMemsetAsync(statep, 0, NBLK * sizeof(unsigned long long));

    hist_kernel<<<4096, TB>>>(hix, n_edges);                               // kernel 1
    scan_kernel<<<NBLK, 1024>>>(n_edges);                                  // kernel 2
    scatter_init_kernel<<<4096, TB>>>(hix, tix, n_edges, W, user, item, A, S0); // kernel 3

    const int spmm_blocks = (N_NODES + 7) / 8;
    const int tile_blocks = (N_NODES + 127) / 128;

    // layer 0
    spmm_kernel<<<spmm_blocks, TB>>>(S0, G);                               // kernel 4 (profiled)
    intent_mma_kernel<<<tile_blocks, TB, SMEM_MMA>>>(A, G, B, S1, nullptr, nullptr);
    // layer 1
    spmm_kernel<<<spmm_blocks, TB>>>(S1, G);
    intent_mma_kernel<<<tile_blocks, TB, SMEM_MMA>>>(B, G, nullptr, nullptr, A, out);
}

// round 16
// speedup vs baseline: 1.4992x; 1.0811x over previous
#include <cuda_runtime.h>
#include <cuda_fp16.h>
#include <math.h>
#include <cstdint>

#define N_USERS 100000
#define N_ITEMS 50000
#define N_NODES 150000
#define EMB 64
#define NINT 128
#define MAX_EDGES 4000000

#define N4 ((N_NODES + 3) / 4)
#define NBLK ((N4 + 1023) / 1024)

// ---------------- static device scratch (256B-aligned: gathered rows must not straddle lines) ----------------
__device__ __align__(256) int    g_deg[N_NODES];
__device__ __align__(256) float  g_dis[N_NODES];
__device__ __align__(256) int    g_rowptr[N_NODES + 1];
__device__ __align__(256) int    g_cursor[N_NODES];
__device__ __align__(256) int    g_ecol[MAX_EDGES];
__device__ __align__(256) volatile unsigned long long g_state[NBLK];
__device__ __align__(256) float  g_embA[(size_t)N_NODES * EMB];
__device__ __align__(256) float  g_embB[(size_t)N_NODES * EMB];
__device__ __align__(256) float  g_gnn [(size_t)N_NODES * EMB];
__device__ __align__(256) __half g_embS0[(size_t)N_NODES * EMB];
__device__ __align__(256) __half g_embS1[(size_t)N_NODES * EMB];
// W pre-staged in mma B-fragment order (fp16 pairs). 16KB each -> L1-resident.
__device__ __align__(256) uint2  g_F1[16 * 4 * 32];   // phase1: [n(16)][kf(4)][lane]
__device__ __align__(256) uint2  g_F2[8 * 8 * 32];    // phase2: [n2(8)][kf2(8)][lane]

// ---------------- packed fp32x2 helpers ----------------
__device__ __forceinline__ unsigned long long fma2(unsigned long long a,
                                                   unsigned long long b,
                                                   unsigned long long c) {
    unsigned long long d;
    asm("fma.rn.f32x2 %0, %1, %2, %3;" : "=l"(d) : "l"(a), "l"(b), "l"(c));
    return d;
}
__device__ __forceinline__ unsigned long long pk2(float x, float y) {
    unsigned long long r;
    asm("mov.b64 %0, {%1, %2};" : "=l"(r) : "f"(x), "f"(y));
    return r;
}
__device__ __forceinline__ float2 upk(unsigned long long v) {
    float2 f;
    asm("mov.b64 {%0, %1}, %2;" : "=f"(f.x), "=f"(f.y) : "l"(v));
    return f;
}
__device__ __forceinline__ unsigned long long h2f2(unsigned int h) {
    float2 f = __half22float2(*(const __half2*)&h);
    return pk2(f.x, f.y);
}
__device__ __forceinline__ uint32_t pack_h2(float x, float y) {
    __half2 h = __floats2half2_rn(x, y);
    return *(uint32_t*)&h;
}

// ---------------- precompute ----------------
__global__ void hist_kernel(const int* __restrict__ h, int n) {
    int stride = gridDim.x * blockDim.x;
    for (int i = blockIdx.x * blockDim.x + threadIdx.x; i < n; i += stride)
        atomicAdd(&g_deg[h[i]], 1);
}

__global__ __launch_bounds__(1024) void scan_kernel(int n_edges) {
    __shared__ int ws[32];
    __shared__ int s_excl;
    const int t = threadIdx.x, b = blockIdx.x;
    const int lane = t & 31, wid = t >> 5;
    const int idx = b * 1024 + t;
    int4 v = (idx < N4) ? ((const int4*)g_deg)[idx] : make_int4(0, 0, 0, 0);
    int s = v.x + v.y + v.z + v.w;
    int x = s;
    #pragma unroll
    for (int o = 1; o < 32; o <<= 1) {
        int y = __shfl_up_sync(0xffffffffu, x, o);
        if (lane >= o) x += y;
    }
    if (lane == 31) ws[wid] = x;
    __syncthreads();
    if (wid == 0) {
        int z = ws[lane];
        #pragma unroll
        for (int o = 1; o < 32; o <<= 1) {
            int y = __shfl_up_sync(0xffffffffu, z, o);
            if (lane >= o) z += y;
        }
        ws[lane] = z;
    }
    __syncthreads();
    const int total = ws[31];

    if (t == 0) {
        if (b == 0) {
            g_state[0] = (2ull << 32) | (unsigned)total;
            s_excl = 0;
        } else {
            g_state[b] = (1ull << 32) | (unsigned)total;
            int excl = 0;
            int p = b - 1;
            while (true) {
                unsigned long long st;
                do { st = g_state[p]; } while ((st >> 32) == 0ull);
                excl += (int)(unsigned)st;
                if ((st >> 32) == 2ull) break;
                p--;
            }
            g_state[b] = (2ull << 32) | (unsigned)(excl + total);
            s_excl = excl;
        }
    }
    __syncthreads();

    int base = s_excl + ((wid > 0) ? ws[wid - 1] : 0) + (x - s);
    if (idx < N4) {
        int i = idx * 4;
        int e0 = base, e1 = e0 + v.x, e2 = e1 + v.y, e3 = e2 + v.z;
        g_rowptr[i + 0] = e0; g_cursor[i + 0] = e0;
        g_rowptr[i + 1] = e1; g_cursor[i + 1] = e1;
        g_rowptr[i + 2] = e2; g_cursor[i + 2] = e2;
        g_rowptr[i + 3] = e3; g_cursor[i + 3] = e3;
        g_dis[i + 0] = (v.x > 0) ? rsqrtf((float)v.x) : 0.0f;
        g_dis[i + 1] = (v.y > 0) ? rsqrtf((float)v.y) : 0.0f;
        g_dis[i + 2] = (v.z > 0) ? rsqrtf((float)v.z) : 0.0f;
        g_dis[i + 3] = (v.w > 0) ? rsqrtf((float)v.w) : 0.0f;
    }
    if (b == 0 && t == 0) g_rowptr[N_NODES] = n_edges;
}

// fused: CSR scatter + embA/S0 init + W fragment staging
__global__ void scatter_init_kernel(const int* __restrict__ h, const int* __restrict__ t,
                                    int n, const float* __restrict__ W,
                                    const float* __restrict__ u, const float* __restrict__ it,
                                    float* __restrict__ embA, __half* __restrict__ S) {
    const int stride = gridDim.x * blockDim.x;
    const int tid0 = blockIdx.x * blockDim.x + threadIdx.x;
    const int total4 = N_NODES * EMB / 4;
    const int ub4 = N_USERS * EMB / 4;
    for (int i = tid0; i < total4; i += stride) {
        float4 v = (i < ub4) ? ((const float4*)u)[i] : ((const float4*)it)[i - ub4];
        ((float4*)embA)[i] = v;
        float d = g_dis[i >> 4];
        ((__half2*)S)[i * 2 + 0] = __floats2half2_rn(v.x * d, v.y * d);
        ((__half2*)S)[i * 2 + 1] = __floats2half2_rn(v.z * d, v.w * d);
    }
    // phase1 B fragments: L = X @ W, B[k][j] = W[k][j]  (W row-major 64x128)
    for (int i = tid0; i < 16 * 4 * 32; i += stride) {
        int pair = i >> 5, l = i & 31;
        int nn = pair >> 2, kf = pair & 3;
        int j = nn * 8 + (l >> 2);
        int k0 = kf * 16 + (l & 3) * 2;
        g_F1[i] = make_uint2(pack_h2(W[k0 * 128 + j], W[(k0 + 1) * 128 + j]),
                             pack_h2(W[(k0 + 8) * 128 + j], W[(k0 + 9) * 128 + j]));
    }
    // phase2 B fragments: Y = P @ W^T, B'[k'][n'] = W[n'][k']
    for (int i = tid0; i < 8 * 8 * 32; i += stride) {
        int pair = i >> 5, l = i & 31;
        int n2 = pair >> 3, kf2 = pair & 7;
        int d = n2 * 8 + (l >> 2);
        int j0 = kf2 * 16 + (l & 3) * 2;
        g_F2[i] = make_uint2(pack_h2(W[d * 128 + j0], W[d * 128 + j0 + 1]),
                             pack_h2(W[d * 128 + j0 + 8], W[d * 128 + j0 + 9]));
    }
    for (int i = tid0; i < n; i += stride) {
        int hh = h[i];
        int pos = atomicAdd(&g_cursor[hh], 1);
        g_ecol[pos] = t[i];
    }
}

// ---------------- SPMM: warp/node, fp16 rows, 8 lanes/row, pipelined ----------------
__global__ __launch_bounds__(256) void spmm_kernel(const __half* __restrict__ S,
                                                   float* __restrict__ xout) {
    const int lane = threadIdx.x & 31;
    const int grp = lane >> 3;
    const int q = lane & 7;
    const int n = (blockIdx.x << 3) + (threadIdx.x >> 5);
    if (n >= N_NODES) return;
    const int beg = g_rowptr[n], end = g_rowptr[n + 1];
    const uint4* S4 = (const uint4*)S;

    unsigned long long a0 = 0ull, a1 = 0ull, a2 = 0ull, a3 = 0ull;
    const unsigned long long one2 = 0x3f8000003f800000ull;
    int j = beg;
    const int nq = (end - beg) >> 2;

    if (nq > 0) {
        int c = g_ecol[j + grp];
        uint4 v = S4[(size_t)c * 8 + q];
        for (int b = 1; b < nq; b++) {
            j += 4;
            int d = g_ecol[j + grp];
            uint4 w = S4[(size_t)d * 8 + q];
            a0 = fma2(h2f2(v.x), one2, a0);
            a1 = fma2(h2f2(v.y), one2, a1);
            a2 = fma2(h2f2(v.z), one2, a2);
            a3 = fma2(h2f2(v.w), one2, a3);
            v = w;
        }
        a0 = fma2(h2f2(v.x), one2, a0);
        a1 = fma2(h2f2(v.y), one2, a1);
        a2 = fma2(h2f2(v.z), one2, a2);
        a3 = fma2(h2f2(v.w), one2, a3);
        j += 4;
    }

    if (j + grp < end) {
        int c = g_ecol[j + grp];
        uint4 v = S4[(size_t)c * 8 + q];
        a0 = fma2(h2f2(v.x), one2, a0);
        a1 = fma2(h2f2(v.y), one2, a1);
        a2 = fma2(h2f2(v.z), one2, a2);
        a3 = fma2(h2f2(v.w), one2, a3);
    }

    float2 f0 = upk(a0), f1 = upk(a1), f2 = upk(a2), f3 = upk(a3);
    #pragma unroll
    for (int o = 8; o <= 16; o <<= 1) {
        f0.x += __shfl_xor_sync(0xffffffffu, f0.x, o);
        f0.y += __shfl_xor_sync(0xffffffffu, f0.y, o);
        f1.x += __shfl_xor_sync(0xffffffffu, f1.x, o);
        f1.y += __shfl_xor_sync(0xffffffffu, f1.y, o);
        f2.x += __shfl_xor_sync(0xffffffffu, f2.x, o);
        f2.y += __shfl_xor_sync(0xffffffffu, f2.y, o);
        f3.x += __shfl_xor_sync(0xffffffffu, f3.x, o);
        f3.y += __shfl_xor_sync(0xffffffffu, f3.y, o);
    }

    if (grp == 0) {
        float dn = g_dis[n];
        float* row = xout + (size_t)n * EMB + q * 8;
        *(float4*)(row)     = make_float4(f0.x * dn, f0.y * dn, f1.x * dn, f1.y * dn);
        *(float4*)(row + 4) = make_float4(f2.x * dn, f2.y * dn, f3.x * dn, f3.y * dn);
    }
}

// ================ mma.sync fp16 intent kernel — no smem, no barriers ================
__device__ __forceinline__ void mma16816(float& c0, float& c1, float& c2, float& c3,
                                         uint32_t a0, uint32_t a1, uint32_t a2, uint32_t a3,
                                         uint32_t b0, uint32_t b1) {
    asm volatile("mma.sync.aligned.m16n8k16.row.col.f32.f16.f16.f32 "
                 "{%0,%1,%2,%3}, {%4,%5,%6,%7}, {%8,%9}, {%0,%1,%2,%3};"
                 : "+f"(c0), "+f"(c1), "+f"(c2), "+f"(c3)
                 : "r"(a0), "r"(a1), "r"(a2), "r"(a3), "r"(b0), "r"(b1));
}

// epilogue modes:
//   layer0: emb_out = gnn + Y; Sout = half(dis * emb_out)
//   layer1: out = (a0row + xin + (gnn + Y)) / 3
__global__ __launch_bounds__(128) void intent_mma_kernel(
    const float* __restrict__ xin, const float* __restrict__ gnn,
    float* __restrict__ emb_out, __half* __restrict__ Sout,
    const float* __restrict__ a0row, float* __restrict__ out) {
    const int tid = threadIdx.x;
    const int w = tid >> 5, lane = tid & 31;
    const int node0 = blockIdx.x * 64;          // 4 warps x 16 rows
    const int m0 = w * 16;
    const int r_lo = node0 + m0 + (lane >> 2);
    const int r_hi = r_lo + 8;
    const int c0 = (lane & 3) * 2;
    const bool v_lo = r_lo < N_NODES, v_hi = r_hi < N_NODES;

    // ---- phase 1: logits acc[16 n-tiles][4]; A frags direct from global X ----
    float acc[16][4];
    #pragma unroll
    for (int n = 0; n < 16; n++) {
        acc[n][0] = 0.f; acc[n][1] = 0.f; acc[n][2] = 0.f; acc[n][3] = 0.f;
    }
    #pragma unroll
    for (int kf = 0; kf < 4; kf++) {
        const int c = kf * 16 + c0;
        float2 xa = v_lo ? *(const float2*)(xin + (size_t)r_lo * EMB + c)     : make_float2(0.f, 0.f);
        float2 xb = v_hi ? *(const float2*)(xin + (size_t)r_hi * EMB + c)     : make_float2(0.f, 0.f);
        float2 xc = v_lo ? *(const float2*)(xin + (size_t)r_lo * EMB + c + 8) : make_float2(0.f, 0.f);
        float2 xd = v_hi ? *(const float2*)(xin + (size_t)r_hi * EMB + c + 8) : make_float2(0.f, 0.f);
        uint32_t a0 = pack_h2(xa.x, xa.y);
        uint32_t a1 = pack_h2(xb.x, xb.y);
        uint32_t a2 = pack_h2(xc.x, xc.y);
        uint32_t a3 = pack_h2(xd.x, xd.y);
        #pragma unroll
        for (int n = 0; n < 16; n++) {
            uint2 b = g_F1[(n * 4 + kf) * 32 + lane];
            mma16816(acc[n][0], acc[n][1], acc[n][2], acc[n][3], a0, a1, a2, a3, b.x, b.y);
        }
    }

    // ---- softmax in registers (quad shuffles) ----
    float mx_lo = -1e30f, mx_hi = -1e30f;
    #pragma unroll
    for (int n = 0; n < 16; n++) {
        mx_lo = fmaxf(mx_lo, fmaxf(acc[n][0], acc[n][1]));
        mx_hi = fmaxf(mx_hi, fmaxf(acc[n][2], acc[n][3]));
    }
    mx_lo = fmaxf(mx_lo, __shfl_xor_sync(0xffffffffu, mx_lo, 1));
    mx_lo = fmaxf(mx_lo, __shfl_xor_sync(0xffffffffu, mx_lo, 2));
    mx_hi = fmaxf(mx_hi, __shfl_xor_sync(0xffffffffu, mx_hi, 1));
    mx_hi = fmaxf(mx_hi, __shfl_xor_sync(0xffffffffu, mx_hi, 2));
    float s_lo = 0.f, s_hi = 0.f;
    #pragma unroll
    for (int n = 0; n < 16; n++) {
        acc[n][0] = __expf(acc[n][0] - mx_lo); s_lo += acc[n][0];
        acc[n][1] = __expf(acc[n][1] - mx_lo); s_lo += acc[n][1];
        acc[n][2] = __expf(acc[n][2] - mx_hi); s_hi += acc[n][2];
        acc[n][3] = __expf(acc[n][3] - mx_hi); s_hi += acc[n][3];
    }
    s_lo += __shfl_xor_sync(0xffffffffu, s_lo, 1);
    s_lo += __shfl_xor_sync(0xffffffffu, s_lo, 2);
    s_hi += __shfl_xor_sync(0xffffffffu, s_hi, 1);
    s_hi += __shfl_xor_sync(0xffffffffu, s_hi, 2);
    const float inv_lo = 1.0f / s_lo, inv_hi = 1.0f / s_hi;

    // ---- repack scaled accs directly as phase2 A fragments ----
    uint32_t A2[8][4];
    #pragma unroll
    for (int kf2 = 0; kf2 < 8; kf2++) {
        A2[kf2][0] = pack_h2(acc[2 * kf2][0] * inv_lo,     acc[2 * kf2][1] * inv_lo);
        A2[kf2][1] = pack_h2(acc[2 * kf2][2] * inv_hi,     acc[2 * kf2][3] * inv_hi);
        A2[kf2][2] = pack_h2(acc[2 * kf2 + 1][0] * inv_lo, acc[2 * kf2 + 1][1] * inv_lo);
        A2[kf2][3] = pack_h2(acc[2 * kf2 + 1][2] * inv_hi, acc[2 * kf2 + 1][3] * inv_hi);
    }

    // ---- phase 2: Y = P @ W^T ----
    float acc2[8][4];
    #pragma unroll
    for (int n2 = 0; n2 < 8; n2++) {
        acc2[n2][0] = 0.f; acc2[n2][1] = 0.f; acc2[n2][2] = 0.f; acc2[n2][3] = 0.f;
    }
    #pragma unroll
    for (int kf2 = 0; kf2 < 8; kf2++) {
        #pragma unroll
        for (int n2 = 0; n2 < 8; n2++) {
            uint2 b = g_F2[(n2 * 8 + kf2) * 32 + lane];
            mma16816(acc2[n2][0], acc2[n2][1], acc2[n2][2], acc2[n2][3],
                     A2[kf2][0], A2[kf2][1], A2[kf2][2], A2[kf2][3], b.x, b.y);
        }
    }

    // ---- epilogue ----
    const float third = 1.0f / 3.0f;
    const float d_lo = (Sout && v_lo) ? g_dis[r_lo] : 0.0f;
    const float d_hi = (Sout && v_hi) ? g_dis[r_hi] : 0.0f;
    #pragma unroll
    for (int n2 = 0; n2 < 8; n2++) {
        int dcol = n2 * 8 + c0;
        if (v_lo) {
            size_t idx = (size_t)r_lo * EMB + dcol;
            float2 g = *(const float2*)(gnn + idx);
            float y0 = acc2[n2][0] + g.x, y1 = acc2[n2][1] + g.y;
            if (emb_out) *(float2*)(emb_out + idx) = make_float2(y0, y1);
            if (Sout) *(__half2*)(Sout + idx) = __floats2half2_rn(y0 * d_lo, y1 * d_lo);
            if (out) {
                float2 a = *(const float2*)(a0row + idx);
                float2 b = *(const float2*)(xin + idx);
                *(float2*)(out + idx) = make_float2((a.x + b.x + y0) * third,
                                                    (a.y + b.y + y1) * third);
            }
        }
        if (v_hi) {
            size_t idx = (size_t)r_hi * EMB + dcol;
            float2 g = *(const float2*)(gnn + idx);
            float y0 = acc2[n2][2] + g.x, y1 = acc2[n2][3] + g.y;
            if (emb_out) *(float2*)(emb_out + idx) = make_float2(y0, y1);
            if (Sout) *(__half2*)(Sout + idx) = __floats2half2_rn(y0 * d_hi, y1 * d_hi);
            if (out) {
                float2 a = *(const float2*)(a0row + idx);
                float2 b = *(const float2*)(xin + idx);
                *(float2*)(out + idx) = make_float2((a.x + b.x + y0) * third,
                                                    (a.y + b.y + y1) * third);
            }
        }
    }
}

// ---------------- launch ----------------
extern "C" void kernel_launch(void* const* d_in, const int* in_sizes, int n_in,
                              void* d_out, int out_size) {
    const float* user = (const float*)d_in[0];
    const float* item = (const float*)d_in[1];
    const float* W    = (const float*)d_in[2];
    const int*   hix  = (const int*)d_in[3];
    const int*   tix  = (const int*)d_in[4];
    const int n_edges = in_sizes[3];
    float* out = (float*)d_out;

    float *A, *B, *G;
    __half *S0, *S1;
    void *degp, *statep;
    cudaGetSymbolAddress((void**)&A, g_embA);
    cudaGetSymbolAddress((void**)&B, g_embB);
    cudaGetSymbolAddress((void**)&G, g_gnn);
    cudaGetSymbolAddress((void**)&S0, g_embS0);
    cudaGetSymbolAddress((void**)&S1, g_embS1);
    cudaGetSymbolAddress(&degp, g_deg);
    cudaGetSymbolAddress(&statep, g_state);

    const int TB = 256;
    cudaMemsetAsync(degp, 0, N_NODES * sizeof(int));
    cudaMemsetAsync(statep, 0, NBLK * sizeof(unsigned long long));

    hist_kernel<<<4096, TB>>>(hix, n_edges);                               // kernel 1
    scan_kernel<<<NBLK, 1024>>>(n_edges);                                  // kernel 2
    scatter_init_kernel<<<4096, TB>>>(hix, tix, n_edges, W, user, item, A, S0); // kernel 3

    const int spmm_blocks = (N_NODES + 7) / 8;
    const int tile_blocks = (N_NODES + 63) / 64;

    // layer 0
    spmm_kernel<<<spmm_blocks, TB>>>(S0, G);                               // kernel 4 (profiled)
    intent_mma_kernel<<<tile_blocks, 128>>>(A, G, B, S1, nullptr, nullptr);
    // layer 1
    spmm_kernel<<<spmm_blocks, TB>>>(S1, G);
    intent_mma_kernel<<<tile_blocks, 128>>>(B, G, nullptr, nullptr, A, out);
}

// round 17
// speedup vs baseline: 1.6249x; 1.0839x over previous
#include <cuda_runtime.h>
#include <cuda_fp16.h>
#include <math.h>
#include <cstdint>

#define N_USERS 100000
#define N_ITEMS 50000
#define N_NODES 150000
#define EMB 64
#define NINT 128
#define MAX_EDGES 4000000

#define N4 ((N_NODES + 3) / 4)
#define NBLK ((N4 + 1023) / 1024)

// ---------------- static device scratch (256B-aligned) ----------------
__device__ __align__(256) int    g_deg[N_NODES];
__device__ __align__(256) float  g_dis[N_NODES];
__device__ __align__(256) int    g_rowptr[N_NODES + 1];
__device__ __align__(256) int    g_rank[MAX_EDGES];
__device__ __align__(256) int    g_ecol[MAX_EDGES];
__device__ __align__(256) volatile unsigned long long g_state[NBLK];
__device__ __align__(256) float  g_embA[(size_t)N_NODES * EMB];
__device__ __align__(256) float  g_embB[(size_t)N_NODES * EMB];
__device__ __align__(256) float  g_gnn [(size_t)N_NODES * EMB];
__device__ __align__(256) __half g_embS0[(size_t)N_NODES * EMB];
__device__ __align__(256) __half g_embS1[(size_t)N_NODES * EMB];
// W pre-staged in mma B-fragment order (fp16 pairs). 16KB each -> L1-resident.
__device__ __align__(256) uint2  g_F1[16 * 4 * 32];   // phase1: [n(16)][kf(4)][lane]
__device__ __align__(256) uint2  g_F2[8 * 8 * 32];    // phase2: [n2(8)][kf2(8)][lane]

// ---------------- packed fp32x2 helpers ----------------
__device__ __forceinline__ unsigned long long fma2(unsigned long long a,
                                                   unsigned long long b,
                                                   unsigned long long c) {
    unsigned long long d;
    asm("fma.rn.f32x2 %0, %1, %2, %3;" : "=l"(d) : "l"(a), "l"(b), "l"(c));
    return d;
}
__device__ __forceinline__ unsigned long long pk2(float x, float y) {
    unsigned long long r;
    asm("mov.b64 %0, {%1, %2};" : "=l"(r) : "f"(x), "f"(y));
    return r;
}
__device__ __forceinline__ float2 upk(unsigned long long v) {
    float2 f;
    asm("mov.b64 {%0, %1}, %2;" : "=f"(f.x), "=f"(f.y) : "l"(v));
    return f;
}
__device__ __forceinline__ unsigned long long h2f2(unsigned int h) {
    float2 f = __half22float2(*(const __half2*)&h);
    return pk2(f.x, f.y);
}
__device__ __forceinline__ uint32_t pack_h2(float x, float y) {
    __half2 h = __floats2half2_rn(x, y);
    return *(uint32_t*)&h;
}
__device__ __forceinline__ float2 h2up(uint32_t h) {
    return __half22float2(*(const __half2*)&h);
}

// ---------------- precompute ----------------
__global__ void hist_kernel(const int* __restrict__ h, int n) {
    int stride = gridDim.x * blockDim.x;
    for (int i = blockIdx.x * blockDim.x + threadIdx.x; i < n; i += stride) {
        int pos = atomicAdd(&g_deg[h[i]], 1);
        g_rank[i] = pos;
    }
}

__global__ __launch_bounds__(1024) void scan_kernel(int n_edges) {
    __shared__ int ws[32];
    __shared__ int s_excl;
    const int t = threadIdx.x, b = blockIdx.x;
    const int lane = t & 31, wid = t >> 5;
    const int idx = b * 1024 + t;
    int4 v = (idx < N4) ? ((const int4*)g_deg)[idx] : make_int4(0, 0, 0, 0);
    int s = v.x + v.y + v.z + v.w;
    int x = s;
    #pragma unroll
    for (int o = 1; o < 32; o <<= 1) {
        int y = __shfl_up_sync(0xffffffffu, x, o);
        if (lane >= o) x += y;
    }
    if (lane == 31) ws[wid] = x;
    __syncthreads();
    if (wid == 0) {
        int z = ws[lane];
        #pragma unroll
        for (int o = 1; o < 32; o <<= 1) {
            int y = __shfl_up_sync(0xffffffffu, z, o);
            if (lane >= o) z += y;
        }
        ws[lane] = z;
    }
    __syncthreads();
    const int total = ws[31];

    if (t == 0) {
        if (b == 0) {
            g_state[0] = (2ull << 32) | (unsigned)total;
            s_excl = 0;
        } else {
            g_state[b] = (1ull << 32) | (unsigned)total;
            int excl = 0;
            int p = b - 1;
            while (true) {
                unsigned long long st;
                do { st = g_state[p]; } while ((st >> 32) == 0ull);
                excl += (int)(unsigned)st;
                if ((st >> 32) == 2ull) break;
                p--;
            }
            g_state[b] = (2ull << 32) | (unsigned)(excl + total);
            s_excl = excl;
        }
    }
    __syncthreads();

    int base = s_excl + ((wid > 0) ? ws[wid - 1] : 0) + (x - s);
    if (idx < N4) {
        int i = idx * 4;
        int e0 = base, e1 = e0 + v.x, e2 = e1 + v.y, e3 = e2 + v.z;
        g_rowptr[i + 0] = e0;
        g_rowptr[i + 1] = e1;
        g_rowptr[i + 2] = e2;
        g_rowptr[i + 3] = e3;
        g_dis[i + 0] = (v.x > 0) ? rsqrtf((float)v.x) : 0.0f;
        g_dis[i + 1] = (v.y > 0) ? rsqrtf((float)v.y) : 0.0f;
        g_dis[i + 2] = (v.z > 0) ? rsqrtf((float)v.z) : 0.0f;
        g_dis[i + 3] = (v.w > 0) ? rsqrtf((float)v.w) : 0.0f;
    }
    if (b == 0 && t == 0) g_rowptr[N_NODES] = n_edges;
}

// fused: CSR scatter (atomic-free, rank precomputed) + embA/S0 init + W fragment staging
__global__ void scatter_init_kernel(const int* __restrict__ h, const int* __restrict__ t,
                                    int n, const float* __restrict__ W,
                                    const float* __restrict__ u, const float* __restrict__ it,
                                    float* __restrict__ embA, __half* __restrict__ S) {
    const int stride = gridDim.x * blockDim.x;
    const int tid0 = blockIdx.x * blockDim.x + threadIdx.x;
    const int total4 = N_NODES * EMB / 4;
    const int ub4 = N_USERS * EMB / 4;
    for (int i = tid0; i < total4; i += stride) {
        float4 v = (i < ub4) ? ((const float4*)u)[i] : ((const float4*)it)[i - ub4];
        ((float4*)embA)[i] = v;
        float d = g_dis[i >> 4];
        ((__half2*)S)[i * 2 + 0] = __floats2half2_rn(v.x * d, v.y * d);
        ((__half2*)S)[i * 2 + 1] = __floats2half2_rn(v.z * d, v.w * d);
    }
    // phase1 B fragments: L = X @ W, B[k][j] = W[k][j]  (W row-major 64x128)
    for (int i = tid0; i < 16 * 4 * 32; i += stride) {
        int pair = i >> 5, l = i & 31;
        int nn = pair >> 2, kf = pair & 3;
        int j = nn * 8 + (l >> 2);
        int k0 = kf * 16 + (l & 3) * 2;
        g_F1[i] = make_uint2(pack_h2(W[k0 * 128 + j], W[(k0 + 1) * 128 + j]),
                             pack_h2(W[(k0 + 8) * 128 + j], W[(k0 + 9) * 128 + j]));
    }
    // phase2 B fragments: Y = P @ W^T, B'[k'][n'] = W[n'][k']
    for (int i = tid0; i < 8 * 8 * 32; i += stride) {
        int pair = i >> 5, l = i & 31;
        int n2 = pair >> 3, kf2 = pair & 7;
        int d = n2 * 8 + (l >> 2);
        int j0 = kf2 * 16 + (l & 3) * 2;
        g_F2[i] = make_uint2(pack_h2(W[d * 128 + j0], W[d * 128 + j0 + 1]),
                             pack_h2(W[d * 128 + j0 + 8], W[d * 128 + j0 + 9]));
    }
    for (int i = tid0; i < n; i += stride) {
        int hh = h[i];
        g_ecol[g_rowptr[hh] + g_rank[i]] = t[i];
    }
}

// ---------------- SPMM: warp/node, fp16 rows, 8 lanes/row, pipelined ----------------
__global__ __launch_bounds__(256) void spmm_kernel(const __half* __restrict__ S,
                                                   float* __restrict__ xout) {
    const int lane = threadIdx.x & 31;
    const int grp = lane >> 3;
    const int q = lane & 7;
    const int n = (blockIdx.x << 3) + (threadIdx.x >> 5);
    if (n >= N_NODES) return;
    const int beg = g_rowptr[n], end = g_rowptr[n + 1];
    const uint4* S4 = (const uint4*)S;

    unsigned long long a0 = 0ull, a1 = 0ull, a2 = 0ull, a3 = 0ull;
    const unsigned long long one2 = 0x3f8000003f800000ull;
    int j = beg;
    const int nq = (end - beg) >> 2;

    if (nq > 0) {
        int c = g_ecol[j + grp];
        uint4 v = S4[(size_t)c * 8 + q];
        for (int b = 1; b < nq; b++) {
            j += 4;
            int d = g_ecol[j + grp];
            uint4 w = S4[(size_t)d * 8 + q];
            a0 = fma2(h2f2(v.x), one2, a0);
            a1 = fma2(h2f2(v.y), one2, a1);
            a2 = fma2(h2f2(v.z), one2, a2);
            a3 = fma2(h2f2(v.w), one2, a3);
            v = w;
        }
        a0 = fma2(h2f2(v.x), one2, a0);
        a1 = fma2(h2f2(v.y), one2, a1);
        a2 = fma2(h2f2(v.z), one2, a2);
        a3 = fma2(h2f2(v.w), one2, a3);
        j += 4;
    }

    if (j + grp < end) {
        int c = g_ecol[j + grp];
        uint4 v = S4[(size_t)c * 8 + q];
        a0 = fma2(h2f2(v.x), one2, a0);
        a1 = fma2(h2f2(v.y), one2, a1);
        a2 = fma2(h2f2(v.z), one2, a2);
        a3 = fma2(h2f2(v.w), one2, a3);
    }

    float2 f0 = upk(a0), f1 = upk(a1), f2 = upk(a2), f3 = upk(a3);
    #pragma unroll
    for (int o = 8; o <= 16; o <<= 1) {
        f0.x += __shfl_xor_sync(0xffffffffu, f0.x, o);
        f0.y += __shfl_xor_sync(0xffffffffu, f0.y, o);
        f1.x += __shfl_xor_sync(0xffffffffu, f1.x, o);
        f1.y += __shfl_xor_sync(0xffffffffu, f1.y, o);
        f2.x += __shfl_xor_sync(0xffffffffu, f2.x, o);
        f2.y += __shfl_xor_sync(0xffffffffu, f2.y, o);
        f3.x += __shfl_xor_sync(0xffffffffu, f3.x, o);
        f3.y += __shfl_xor_sync(0xffffffffu, f3.y, o);
    }

    if (grp == 0) {
        float dn = g_dis[n];
        float* row = xout + (size_t)n * EMB + q * 8;
        *(float4*)(row)     = make_float4(f0.x * dn, f0.y * dn, f1.x * dn, f1.y * dn);
        *(float4*)(row + 4) = make_float4(f2.x * dn, f2.y * dn, f3.x * dn, f3.y * dn);
    }
}

// ================ mma.sync fp16 intent kernel — no smem, no barriers ================
__device__ __forceinline__ void mma16816(float& c0, float& c1, float& c2, float& c3,
                                         uint32_t a0, uint32_t a1, uint32_t a2, uint32_t a3,
                                         uint32_t b0, uint32_t b1) {
    asm volatile("mma.sync.aligned.m16n8k16.row.col.f32.f16.f16.f32 "
                 "{%0,%1,%2,%3}, {%4,%5,%6,%7}, {%8,%9}, {%0,%1,%2,%3};"
                 : "+f"(c0), "+f"(c1), "+f"(c2), "+f"(c3)
                 : "r"(a0), "r"(a1), "r"(a2), "r"(a3), "r"(b0), "r"(b1));
}

// FINAL=false (layer0): emb_out = gnn + Y; Sout = half(dis * emb_out)
// FINAL=true  (layer1): out = (a0row + xin + (gnn + Y)) / 3, xin reused from fp16 frags
template <bool FINAL>
__global__ __launch_bounds__(128) void intent_mma_kernel(
    const float* __restrict__ xin, const float* __restrict__ gnn,
    float* __restrict__ emb_out, __half* __restrict__ Sout,
    const float* __restrict__ a0row, float* __restrict__ out) {
    const int tid = threadIdx.x;
    const int w = tid >> 5, lane = tid & 31;
    const int node0 = blockIdx.x * 64;          // 4 warps x 16 rows
    const int m0 = w * 16;
    const int r_lo = node0 + m0 + (lane >> 2);
    const int r_hi = r_lo + 8;
    const int c0 = (lane & 3) * 2;
    const bool v_lo = r_lo < N_NODES, v_hi = r_hi < N_NODES;

    // ---- phase 1: logits acc[16 n-tiles][4]; A frags direct from global X ----
    float acc[16][4];
    #pragma unroll
    for (int n = 0; n < 16; n++) {
        acc[n][0] = 0.f; acc[n][1] = 0.f; acc[n][2] = 0.f; acc[n][3] = 0.f;
    }
    uint32_t XA[4][4];   // stashed A fragments (used by FINAL epilogue)
    #pragma unroll
    for (int kf = 0; kf < 4; kf++) {
        const int c = kf * 16 + c0;
        float2 xa = v_lo ? *(const float2*)(xin + (size_t)r_lo * EMB + c)     : make_float2(0.f, 0.f);
        float2 xb = v_hi ? *(const float2*)(xin + (size_t)r_hi * EMB + c)     : make_float2(0.f, 0.f);
        float2 xc = v_lo ? *(const float2*)(xin + (size_t)r_lo * EMB + c + 8) : make_float2(0.f, 0.f);
        float2 xd = v_hi ? *(const float2*)(xin + (size_t)r_hi * EMB + c + 8) : make_float2(0.f, 0.f);
        uint32_t a0 = pack_h2(xa.x, xa.y);
        uint32_t a1 = pack_h2(xb.x, xb.y);
        uint32_t a2 = pack_h2(xc.x, xc.y);
        uint32_t a3 = pack_h2(xd.x, xd.y);
        if (FINAL) { XA[kf][0] = a0; XA[kf][1] = a1; XA[kf][2] = a2; XA[kf][3] = a3; }
        #pragma unroll
        for (int n = 0; n < 16; n++) {
            uint2 b = g_F1[(n * 4 + kf) * 32 + lane];
            mma16816(acc[n][0], acc[n][1], acc[n][2], acc[n][3], a0, a1, a2, a3, b.x, b.y);
        }
    }

    // ---- softmax in registers (quad shuffles) ----
    float mx_lo = -1e30f, mx_hi = -1e30f;
    #pragma unroll
    for (int n = 0; n < 16; n++) {
        mx_lo = fmaxf(mx_lo, fmaxf(acc[n][0], acc[n][1]));
        mx_hi = fmaxf(mx_hi, fmaxf(acc[n][2], acc[n][3]));
    }
    mx_lo = fmaxf(mx_lo, __shfl_xor_sync(0xffffffffu, mx_lo, 1));
    mx_lo = fmaxf(mx_lo, __shfl_xor_sync(0xffffffffu, mx_lo, 2));
    mx_hi = fmaxf(mx_hi, __shfl_xor_sync(0xffffffffu, mx_hi, 1));
    mx_hi = fmaxf(mx_hi, __shfl_xor_sync(0xffffffffu, mx_hi, 2));
    float s_lo = 0.f, s_hi = 0.f;
    #pragma unroll
    for (int n = 0; n < 16; n++) {
        acc[n][0] = __expf(acc[n][0] - mx_lo); s_lo += acc[n][0];
        acc[n][1] = __expf(acc[n][1] - mx_lo); s_lo += acc[n][1];
        acc[n][2] = __expf(acc[n][2] - mx_hi); s_hi += acc[n][2];
        acc[n][3] = __expf(acc[n][3] - mx_hi); s_hi += acc[n][3];
    }
    s_lo += __shfl_xor_sync(0xffffffffu, s_lo, 1);
    s_lo += __shfl_xor_sync(0xffffffffu, s_lo, 2);
    s_hi += __shfl_xor_sync(0xffffffffu, s_hi, 1);
    s_hi += __shfl_xor_sync(0xffffffffu, s_hi, 2);
    const float inv_lo = 1.0f / s_lo, inv_hi = 1.0f / s_hi;

    // ---- repack scaled accs directly as phase2 A fragments ----
    uint32_t A2[8][4];
    #pragma unroll
    for (int kf2 = 0; kf2 < 8; kf2++) {
        A2[kf2][0] = pack_h2(acc[2 * kf2][0] * inv_lo,     acc[2 * kf2][1] * inv_lo);
        A2[kf2][1] = pack_h2(acc[2 * kf2][2] * inv_hi,     acc[2 * kf2][3] * inv_hi);
        A2[kf2][2] = pack_h2(acc[2 * kf2 + 1][0] * inv_lo, acc[2 * kf2 + 1][1] * inv_lo);
        A2[kf2][3] = pack_h2(acc[2 * kf2 + 1][2] * inv_hi, acc[2 * kf2 + 1][3] * inv_hi);
    }

    // ---- phase 2: Y = P @ W^T ----
    float acc2[8][4];
    #pragma unroll
    for (int n2 = 0; n2 < 8; n2++) {
        acc2[n2][0] = 0.f; acc2[n2][1] = 0.f; acc2[n2][2] = 0.f; acc2[n2][3] = 0.f;
    }
    #pragma unroll
    for (int kf2 = 0; kf2 < 8; kf2++) {
        #pragma unroll
        for (int n2 = 0; n2 < 8; n2++) {
            uint2 b = g_F2[(n2 * 8 + kf2) * 32 + lane];
            mma16816(acc2[n2][0], acc2[n2][1], acc2[n2][2], acc2[n2][3],
                     A2[kf2][0], A2[kf2][1], A2[kf2][2], A2[kf2][3], b.x, b.y);
        }
    }

    // ---- epilogue ----
    const float third = 1.0f / 3.0f;
    const float d_lo = (!FINAL && v_lo) ? g_dis[r_lo] : 0.0f;
    const float d_hi = (!FINAL && v_hi) ? g_dis[r_hi] : 0.0f;
    #pragma unroll
    for (int n2 = 0; n2 < 8; n2++) {
        int dcol = n2 * 8 + c0;
        if (v_lo) {
            size_t idx = (size_t)r_lo * EMB + dcol;
            float2 g = *(const float2*)(gnn + idx);
            float y0 = acc2[n2][0] + g.x, y1 = acc2[n2][1] + g.y;
            if (!FINAL) {
                *(float2*)(emb_out + idx) = make_float2(y0, y1);
                *(__half2*)(Sout + idx) = __floats2half2_rn(y0 * d_lo, y1 * d_lo);
            } else {
                float2 a = *(const float2*)(a0row + idx);
                float2 b = h2up(XA[n2 >> 1][(n2 & 1) * 2]);
                *(float2*)(out + idx) = make_float2((a.x + b.x + y0) * third,
                                                    (a.y + b.y + y1) * third);
            }
        }
        if (v_hi) {
            size_t idx = (size_t)r_hi * EMB + dcol;
            float2 g = *(const float2*)(gnn + idx);
            float y0 = acc2[n2][2] + g.x, y1 = acc2[n2][3] + g.y;
            if (!FINAL) {
                *(float2*)(emb_out + idx) = make_float2(y0, y1);
                *(__half2*)(Sout + idx) = __floats2half2_rn(y0 * d_hi, y1 * d_hi);
            } else {
                float2 a = *(const float2*)(a0row + idx);
                float2 b = h2up(XA[n2 >> 1][(n2 & 1) * 2 + 1]);
                *(float2*)(out + idx) = make_float2((a.x + b.x + y0) * third,
                                                    (a.y + b.y + y1) * third);
            }
        }
    }
}

// ---------------- launch ----------------
extern "C" void kernel_launch(void* const* d_in, const int* in_sizes, int n_in,
                              void* d_out, int out_size) {
    const float* user = (const float*)d_in[0];
    const float* item = (const float*)d_in[1];
    const float* W    = (const float*)d_in[2];
    const int*   hix  = (const int*)d_in[3];
    const int*   tix  = (const int*)d_in[4];
    const int n_edges = in_sizes[3];
    float* out = (float*)d_out;

    float *A, *B, *G;
    __half *S0, *S1;
    void *degp, *statep;
    cudaGetSymbolAddress((void**)&A, g_embA);
    cudaGetSymbolAddress((void**)&B, g_embB);
    cudaGetSymbolAddress((void**)&G, g_gnn);
    cudaGetSymbolAddress((void**)&S0, g_embS0);
    cudaGetSymbolAddress((void**)&S1, g_embS1);
    cudaGetSymbolAddress(&degp, g_deg);
    cudaGetSymbolAddress(&statep, g_state);

    const int TB = 256;
    cudaMemsetAsync(degp, 0, N_NODES * sizeof(int));
    cudaMemsetAsync(statep, 0, NBLK * sizeof(unsigned long long));

    hist_kernel<<<4096, TB>>>(hix, n_edges);                               // kernel 1
    scan_kernel<<<NBLK, 1024>>>(n_edges);                                  // kernel 2
    scatter_init_kernel<<<4096, TB>>>(hix, tix, n_edges, W, user, item, A, S0); // kernel 3

    const int spmm_blocks = (N_NODES + 7) / 8;
    const int tile_blocks = (N_NODES + 63) / 64;

    // layer 0
    spmm_kernel<<<spmm_blocks, TB>>>(S0, G);                               // kernel 4 (profiled)
    intent_mma_kernel<false><<<tile_blocks, 128>>>(A, G, B, S1, nullptr, nullptr);
    // layer 1
    spmm_kernel<<<spmm_blocks, TB>>>(S1, G);
    intent_mma_kernel<true><<<tile_blocks, 128>>>(B, G, nullptr, nullptr, A, out);
}